// round 13
// baseline (speedup 1.0000x reference)
#include <cuda_runtime.h>
#include <cuda_fp16.h>
#include <cstdint>
#include <math.h>

// ---------------- problem constants ----------------
#define Bb   4
#define Ss   1024
#define Ee   1024
#define Hh   16
#define HDs  64
#define MTOT 4096      // B*S
#define E3   3072      // 3*E
#define Kdim 1024

// ---------------- scratch (device globals, fp16) ----------------
__device__ __half  g_xh [MTOT * Ee];     // X fp16 (QKV GEMM A)
__device__ __half  g_qh [MTOT * Ee];     // Q fp16
__device__ __half  g_kh [MTOT * Ee];     // K fp16
__device__ __half  g_vh [MTOT * Ee];     // V fp16, row-major [s][hd]
__device__ __half  g_wq [E3 * Ee];       // Wqkv^T fp16
__device__ __half  g_wp [Ee * Ee];       // Wproj^T fp16
__device__ __half  g_oh [MTOT * Ee];     // attention output fp16 (proj A)

// ---------------- helpers ----------------
__device__ __forceinline__ void mma16816(float* c, const uint32_t* a, const uint32_t* b)
{
    asm volatile(
        "mma.sync.aligned.m16n8k16.row.col.f32.f16.f16.f32 "
        "{%0,%1,%2,%3}, {%4,%5,%6,%7}, {%8,%9}, {%0,%1,%2,%3};"
        : "+f"(c[0]), "+f"(c[1]), "+f"(c[2]), "+f"(c[3])
        : "r"(a[0]), "r"(a[1]), "r"(a[2]), "r"(a[3]), "r"(b[0]), "r"(b[1]));
}
__device__ __forceinline__ void ldsm4(uint32_t& r0, uint32_t& r1, uint32_t& r2, uint32_t& r3,
                                      uint32_t addr)
{
    asm volatile("ldmatrix.sync.aligned.m8n8.x4.shared.b16 {%0,%1,%2,%3}, [%4];"
                 : "=r"(r0), "=r"(r1), "=r"(r2), "=r"(r3) : "r"(addr));
}
__device__ __forceinline__ void ldsm4t(uint32_t& r0, uint32_t& r1, uint32_t& r2, uint32_t& r3,
                                       uint32_t addr)
{
    asm volatile("ldmatrix.sync.aligned.m8n8.x4.trans.shared.b16 {%0,%1,%2,%3}, [%4];"
                 : "=r"(r0), "=r"(r1), "=r"(r2), "=r"(r3) : "r"(addr));
}
__device__ __forceinline__ void cp16(uint32_t saddr, const void* g)
{
    asm volatile("cp.async.cg.shared.global [%0], [%1], 16;"
                 :: "r"(saddr), "l"(g));
}
__device__ __forceinline__ uint32_t smem_u32(const void* p) {
    uint32_t a;
    asm("{ .reg .u64 t; cvta.to.shared.u64 t, %1; cvt.u32.u64 %0, t; }"
        : "=r"(a) : "l"(p));
    return a;
}
__device__ __forceinline__ uint32_t pack2h(float f0, float f1)
{
    __half2 p = __floats2half2_rn(f0, f1);
    return *(uint32_t*)&p;
}

// ---------------- fp32 -> fp16 convert ----------------
__global__ __launch_bounds__(256)
void to_half(const float* __restrict__ x, __half* __restrict__ h, int n)
{
    int i = (blockIdx.x * 256 + threadIdx.x) * 4;
    if (i >= n) return;
    float4 v = *(const float4*)(x + i);
    __half hh[4] = {__float2half_rn(v.x), __float2half_rn(v.y),
                    __float2half_rn(v.z), __float2half_rn(v.w)};
    *(uint2*)(h + i) = *(uint2*)hh;
}

// ---------------- transpose W: W[K][N] -> T[N][K] (fp16) ----------------
__global__ __launch_bounds__(256)
void transpose_h(const float* __restrict__ W, __half* __restrict__ T, int K, int N)
{
    __shared__ float tile[32][33];
    int n0 = blockIdx.x * 32, k0 = blockIdx.y * 32;
    int tx = threadIdx.x, ty = threadIdx.y;
#pragma unroll
    for (int i = 0; i < 32; i += 8)
        tile[ty + i][tx] = W[(size_t)(k0 + ty + i) * N + n0 + tx];
    __syncthreads();
#pragma unroll
    for (int i = 0; i < 32; i += 8) {
        int n = n0 + ty + i, k = k0 + tx;
        T[(size_t)n * K + k] = __float2half_rn(tile[tx][ty + i]);
    }
}

// ---------------- fp16 single-pass GEMM: block tile 256x128, 8 warps ----------------
// FUSE=0: C fp32 out. FUSE=1: QKV epilogue — sec0->qh, sec1->kh, sec2->vh (fp16, stride 1024).
#define GBK      32
#define GSTRIDE  40
#define ROWB     (GSTRIDE * 2)             // 80 B per k-row
#define ARR_A    (256 * ROWB)              // 20480 B
#define ARR_BB   (128 * ROWB)              // 10240 B
#define STAGE_B  (ARR_A + ARR_BB)          // 30720 B
#define GEMM_SMEM (2 * STAGE_B)            // 61440 B

template<bool FUSE>
__global__ __launch_bounds__(256, 1)
void gemm_mma(const __half* __restrict__ A, const __half* __restrict__ B,
              const float* __restrict__ bias, float* __restrict__ C, int N,
              __half* __restrict__ qh, __half* __restrict__ kh, __half* __restrict__ vh)
{
    extern __shared__ char smem[];
    const uint32_t sb = smem_u32(smem);
    const int tid  = threadIdx.x;
    const int wid  = tid >> 5, lane = tid & 31;
    const int wm   = wid >> 1, wn = wid & 1;          // warp grid 4x2, tile 64x64
    const int g    = lane >> 2, tig = lane & 3;
    const int bm   = blockIdx.y * 256, bn = blockIdx.x * 128;
    const int NC   = Kdim / GBK;

    const int qd = lane >> 3, il = lane & 7;
    const uint32_t offA = (uint32_t)((wm * 64 + il + (qd & 1) * 8) * ROWB + ((qd >> 1) * 8) * 2);
    const uint32_t offB = (uint32_t)((wn * 64 + il + (qd >> 1) * 8) * ROWB + ((qd & 1) * 8) * 2);

    float acc[4][8][4];
#pragma unroll
    for (int im = 0; im < 4; im++)
#pragma unroll
        for (int in = 0; in < 8; in++)
#pragma unroll
            for (int q = 0; q < 4; q++) acc[im][in][q] = 0.0f;

    auto prefetch = [&](int c, int st) {
#pragma unroll
        for (int i = 0; i < 6; i++) {
            int idx = tid + i * 256;        // 0..1535 16B-units (A:1024, B:512)
            const __half* gp;
            uint32_t sa;
            size_t kbase = (size_t)c * GBK;
            if (idx < 1024) {
                int row = idx >> 2, seg = idx & 3;
                gp = A + (size_t)(bm + row) * Kdim + kbase + seg * 8;
                sa = sb + st * STAGE_B + row * ROWB + seg * 16;
            } else {
                int e = idx - 1024;
                int row = e >> 2, seg = e & 3;
                gp = B + (size_t)(bn + row) * Kdim + kbase + seg * 8;
                sa = sb + st * STAGE_B + ARR_A + row * ROWB + seg * 16;
            }
            cp16(sa, gp);
        }
        asm volatile("cp.async.commit_group;");
    };

    prefetch(0, 0);

    for (int c = 0; c < NC; c++) {
        const int st = c & 1;
        if (c + 1 < NC) {
            prefetch(c + 1, (c + 1) & 1);
            asm volatile("cp.async.wait_group 1;");
        } else {
            asm volatile("cp.async.wait_group 0;");
        }
        __syncthreads();

        const uint32_t stb = sb + st * STAGE_B;

#pragma unroll
        for (int kk = 0; kk < GBK; kk += 16) {
            const uint32_t kb = (uint32_t)(kk * 2);
            uint32_t a[4][4], bf[8][2];
#pragma unroll
            for (int p = 0; p < 4; p++)
                ldsm4(bf[2*p][0], bf[2*p][1], bf[2*p+1][0], bf[2*p+1][1],
                      stb + ARR_A + offB + p * (16 * ROWB) + kb);
#pragma unroll
            for (int im = 0; im < 4; im++)
                ldsm4(a[im][0], a[im][1], a[im][2], a[im][3],
                      stb + offA + im * (16 * ROWB) + kb);
#pragma unroll
            for (int im = 0; im < 4; im++)
#pragma unroll
                for (int in = 0; in < 8; in++)
                    mma16816(acc[im][in], a[im], bf[in]);
        }
        __syncthreads();
    }

    // epilogue
    __half* d = qh;
    if (FUSE) {
        int sec = bn >> 10;                // uniform per CTA
        if (sec == 1) d = kh;
        else if (sec == 2) d = vh;
    }
#pragma unroll
    for (int im = 0; im < 4; im++) {
        int r = bm + wm * 64 + im * 16 + g;
#pragma unroll
        for (int in = 0; in < 8; in++) {
            int ccol = bn + wn * 64 + in * 8 + 2 * tig;
            float2 b01 = *(const float2*)&bias[ccol];
            float2 o0 = make_float2(acc[im][in][0] + b01.x, acc[im][in][1] + b01.y);
            float2 o1 = make_float2(acc[im][in][2] + b01.x, acc[im][in][3] + b01.y);
            if (!FUSE) {
                *(float2*)&C[(size_t)r * N + ccol]       = o0;
                *(float2*)&C[(size_t)(r + 8) * N + ccol] = o1;
            } else {
                int col = ccol & 1023;
                *(uint32_t*)&d[(size_t)r * 1024 + col]       = pack2h(o0.x, o0.y);
                *(uint32_t*)&d[(size_t)(r + 8) * 1024 + col] = pack2h(o1.x, o1.y);
            }
        }
    }
}

// ---------------- fp16 single-pass flash attention (unchanged from R12) ----------------
#define AKVROW 144
#define AARR   9216
#define AST    (2 * AARR)                  // 18432
#define ATTN_SMEM (3 * AST)                // 55296

__global__ __launch_bounds__(256, 1)
void attn_mma(const __half* __restrict__ qh,
              const __half* __restrict__ kh, const __half* __restrict__ vh,
              const int* __restrict__ mask, __half* __restrict__ oh)
{
    extern __shared__ char asmem[];
    __shared__ int sMask[3][64];
    const uint32_t sb = smem_u32(asmem);
    const uint32_t mb = smem_u32(&sMask[0][0]);

    const int tid = threadIdx.x, wid = tid >> 5, lane = tid & 31;
    const int g = lane >> 2, tig = lane & 3;
    const int qd = lane >> 3, il = lane & 7;
    const uint32_t offKV  = (uint32_t)((il + (qd >> 1) * 8) * AKVROW + ((qd & 1) * 8) * 2);
    const uint32_t offKVt = (uint32_t)((il + (qd & 1) * 8) * AKVROW + ((qd >> 1) * 8) * 2);

    const int qt = gridDim.x - 1 - blockIdx.x;   // heavy tiles launch first
    const int bh = blockIdx.y;
    const int b = bh >> 4, h = bh & 15;
    const int q0 = qt * 128;
    const int wrow = q0 + wid * 16;
    const float scale = 0.125f;

    uint32_t aq[4][4];
    {
        const __half* qb = qh + (size_t)(b * Ss + wrow) * Ee + h * 64;
#pragma unroll
        for (int s = 0; s < 4; s++) {
            int k0 = s * 16 + 2 * tig;
            aq[s][0] = *(const uint32_t*)&qb[(size_t)(g    ) * Ee + k0];
            aq[s][1] = *(const uint32_t*)&qb[(size_t)(g + 8) * Ee + k0];
            aq[s][2] = *(const uint32_t*)&qb[(size_t)(g    ) * Ee + k0 + 8];
            aq[s][3] = *(const uint32_t*)&qb[(size_t)(g + 8) * Ee + k0 + 8];
        }
    }

    auto prefetch = [&](int j) {
        const int kv0 = j * 64;
        const int st = j % 3;
        const uint32_t stb = sb + st * AST;
#pragma unroll
        for (int i = 0; i < 4; i++) {
            int idx = tid + i * 256;
            int arr = idx >> 9;             // 0:K 1:V
            int e   = idx & 511;
            int row = e >> 3;
            int segB = (e & 7) * 16;
            const __half* gp = (arr == 0 ? kh : vh)
                             + (size_t)(b * Ss + kv0 + row) * Ee + h * 64 + segB / 2;
            cp16(stb + arr * AARR + row * AKVROW + segB, gp);
        }
        if (tid < 16)
            cp16(mb + st * 256 + tid * 16, &mask[b * Ss + kv0 + tid * 4]);
        asm volatile("cp.async.commit_group;");
    };

    float m0 = -1e30f, m1 = -1e30f, l0 = 0.0f, l1 = 0.0f;
    float o[8][4];
#pragma unroll
    for (int t = 0; t < 8; t++)
#pragma unroll
        for (int e = 0; e < 4; e++) o[t][e] = 0.0f;

    const int row0 = wrow + g, row1 = wrow + 8 + g;
    const int ntiles = (qt + 1) * 2;

    prefetch(0);

    for (int j = 0; j < ntiles; j++) {
        const int kv0 = j * 64;
        const int st = j % 3;
        if (j + 1 < ntiles) {
            prefetch(j + 1);
            asm volatile("cp.async.wait_group 1;");
        } else {
            asm volatile("cp.async.wait_group 0;");
        }
        __syncthreads();

        const uint32_t stb = sb + st * AST;
        const int* msk = sMask[st];

        float c[8][4];
#pragma unroll
        for (int t = 0; t < 8; t++)
#pragma unroll
            for (int e = 0; e < 4; e++) c[t][e] = 0.0f;

#pragma unroll
        for (int s = 0; s < 4; s++) {
            const uint32_t kb = (uint32_t)(s * 32);
            uint32_t kf[8][2];
#pragma unroll
            for (int p = 0; p < 4; p++)
                ldsm4(kf[2*p][0], kf[2*p][1], kf[2*p+1][0], kf[2*p+1][1],
                      stb + offKV + p * (16 * AKVROW) + kb);
#pragma unroll
            for (int t = 0; t < 8; t++)
                mma16816(c[t], aq[s], kf[t]);
        }

#pragma unroll
        for (int t = 0; t < 8; t++) {
            int lc0 = t * 8 + 2 * tig;
            int col0 = kv0 + lc0, col1 = col0 + 1;
            bool v0 = msk[lc0] != 0, v1 = msk[lc0 + 1] != 0;
            c[t][0] = (v0 && col0 <= row0) ? c[t][0] * scale : -1e30f;
            c[t][1] = (v1 && col1 <= row0) ? c[t][1] * scale : -1e30f;
            c[t][2] = (v0 && col0 <= row1) ? c[t][2] * scale : -1e30f;
            c[t][3] = (v1 && col1 <= row1) ? c[t][3] * scale : -1e30f;
        }

        float ml0 = -1e30f, ml1 = -1e30f;
#pragma unroll
        for (int t = 0; t < 8; t++) {
            ml0 = fmaxf(ml0, fmaxf(c[t][0], c[t][1]));
            ml1 = fmaxf(ml1, fmaxf(c[t][2], c[t][3]));
        }
        ml0 = fmaxf(ml0, __shfl_xor_sync(0xffffffffu, ml0, 1));
        ml0 = fmaxf(ml0, __shfl_xor_sync(0xffffffffu, ml0, 2));
        ml1 = fmaxf(ml1, __shfl_xor_sync(0xffffffffu, ml1, 1));
        ml1 = fmaxf(ml1, __shfl_xor_sync(0xffffffffu, ml1, 2));

        float mn0 = fmaxf(m0, ml0), mn1 = fmaxf(m1, ml1);
        float alpha0 = __expf(m0 - mn0), alpha1 = __expf(m1 - mn1);
        m0 = mn0; m1 = mn1;

        float rs0 = 0.0f, rs1 = 0.0f;
#pragma unroll
        for (int t = 0; t < 8; t++) {
            c[t][0] = __expf(c[t][0] - m0); rs0 += c[t][0];
            c[t][1] = __expf(c[t][1] - m0); rs0 += c[t][1];
            c[t][2] = __expf(c[t][2] - m1); rs1 += c[t][2];
            c[t][3] = __expf(c[t][3] - m1); rs1 += c[t][3];
        }
        rs0 += __shfl_xor_sync(0xffffffffu, rs0, 1);
        rs0 += __shfl_xor_sync(0xffffffffu, rs0, 2);
        rs1 += __shfl_xor_sync(0xffffffffu, rs1, 1);
        rs1 += __shfl_xor_sync(0xffffffffu, rs1, 2);

        l0 = l0 * alpha0 + rs0;
        l1 = l1 * alpha1 + rs1;
#pragma unroll
        for (int t = 0; t < 8; t++) {
            o[t][0] *= alpha0; o[t][1] *= alpha0;
            o[t][2] *= alpha1; o[t][3] *= alpha1;
        }

#pragma unroll
        for (int s = 0; s < 4; s++) {
            uint32_t ap[4];
            ap[0] = pack2h(c[2 * s][0],     c[2 * s][1]);
            ap[1] = pack2h(c[2 * s][2],     c[2 * s][3]);
            ap[2] = pack2h(c[2 * s + 1][0], c[2 * s + 1][1]);
            ap[3] = pack2h(c[2 * s + 1][2], c[2 * s + 1][3]);
            const uint32_t krow = (uint32_t)(s * 16 * AKVROW);
            uint32_t vf[8][2];
#pragma unroll
            for (int p = 0; p < 4; p++)
                ldsm4t(vf[2*p][0], vf[2*p][1], vf[2*p+1][0], vf[2*p+1][1],
                       stb + AARR + offKVt + krow + p * 32);
#pragma unroll
            for (int t = 0; t < 8; t++)
                mma16816(o[t], ap, vf[t]);
        }
    }

    float inv0 = 1.0f / l0, inv1 = 1.0f / l1;
    size_t base0 = (size_t)(b * Ss + row0) * Ee + h * 64;
    size_t base1 = (size_t)(b * Ss + row1) * Ee + h * 64;
#pragma unroll
    for (int t = 0; t < 8; t++) {
        int cc = t * 8 + 2 * tig;
        *(uint32_t*)&oh[base0 + cc] = pack2h(o[t][0] * inv0, o[t][1] * inv0);
        *(uint32_t*)&oh[base1 + cc] = pack2h(o[t][2] * inv1, o[t][3] * inv1);
    }
}

// ---------------- launch ----------------
extern "C" void kernel_launch(void* const* d_in, const int* in_sizes, int n_in,
                              void* d_out, int out_size)
{
    const float* X     = (const float*)d_in[0];
    const int*   mask  = (const int*)  d_in[1];
    const float* Wqkv  = (const float*)d_in[2];
    const float* bqkv  = (const float*)d_in[3];
    const float* Wproj = (const float*)d_in[4];
    const float* bproj = (const float*)d_in[5];
    float* out = (float*)d_out;

    __half *xh, *qh, *kh, *vh, *wq, *wp, *oh;
    cudaGetSymbolAddress((void**)&xh, g_xh);
    cudaGetSymbolAddress((void**)&qh, g_qh);
    cudaGetSymbolAddress((void**)&kh, g_kh);
    cudaGetSymbolAddress((void**)&vh, g_vh);
    cudaGetSymbolAddress((void**)&wq, g_wq);
    cudaGetSymbolAddress((void**)&wp, g_wp);
    cudaGetSymbolAddress((void**)&oh, g_oh);

    cudaFuncSetAttribute(gemm_mma<true>,  cudaFuncAttributeMaxDynamicSharedMemorySize, GEMM_SMEM);
    cudaFuncSetAttribute(gemm_mma<false>, cudaFuncAttributeMaxDynamicSharedMemorySize, GEMM_SMEM);
    cudaFuncSetAttribute(attn_mma, cudaFuncAttributeMaxDynamicSharedMemorySize, ATTN_SMEM);

    // prep: X -> fp16; transpose weights -> fp16
    to_half<<<(MTOT * Ee) / 4 / 256, 256>>>(X, xh, MTOT * Ee);
    {
        dim3 blk(32, 8);
        transpose_h<<<dim3(E3 / 32, Kdim / 32), blk>>>(Wqkv, wq, Kdim, E3);
        transpose_h<<<dim3(Ee / 32, Kdim / 32), blk>>>(Wproj, wp, Kdim, Ee);
    }

    // 1) QKV = X @ Wqkv + b (fp16, 256x128 tiles), fused epilogue -> q/k/v fp16
    gemm_mma<true><<<dim3(E3 / 128, MTOT / 256), 256, GEMM_SMEM>>>(
        xh, wq, bqkv, nullptr, E3, qh, kh, vh);

    // 2) flash attention (fp16 single-pass)
    attn_mma<<<dim3(Ss / 128, Bb * Hh), 256, ATTN_SMEM>>>(qh, kh, vh, mask, oh);

    // 3) out = attn @ Wproj + b (fp16, 256x128 tiles, fp32 out; 128 CTAs = 1 wave)
    gemm_mma<false><<<dim3(Ee / 128, MTOT / 256), 256, GEMM_SMEM>>>(
        oh, wp, bproj, out, Ee, qh, kh, vh);
}

// round 14
// speedup vs baseline: 1.2168x; 1.2168x over previous
#include <cuda_runtime.h>
#include <cuda_fp16.h>
#include <cstdint>
#include <math.h>

// ---------------- problem constants ----------------
#define Bb   4
#define Ss   1024
#define Ee   1024
#define Hh   16
#define HDs  64
#define MTOT 4096      // B*S
#define E3   3072      // 3*E
#define Kdim 1024

// ---------------- scratch (device globals, fp16) ----------------
__device__ __half  g_xh [MTOT * Ee];     // X fp16 (QKV GEMM A)
__device__ __half  g_qh [MTOT * Ee];     // Q fp16
__device__ __half  g_kh [MTOT * Ee];     // K fp16
__device__ __half  g_vh [MTOT * Ee];     // V fp16, row-major [s][hd]
__device__ __half  g_wq [E3 * Ee];       // Wqkv^T fp16
__device__ __half  g_wp [Ee * Ee];       // Wproj^T fp16
__device__ __half  g_oh [MTOT * Ee];     // attention output fp16 (proj A)

// ---------------- helpers ----------------
__device__ __forceinline__ void mma16816(float* c, const uint32_t* a, const uint32_t* b)
{
    asm volatile(
        "mma.sync.aligned.m16n8k16.row.col.f32.f16.f16.f32 "
        "{%0,%1,%2,%3}, {%4,%5,%6,%7}, {%8,%9}, {%0,%1,%2,%3};"
        : "+f"(c[0]), "+f"(c[1]), "+f"(c[2]), "+f"(c[3])
        : "r"(a[0]), "r"(a[1]), "r"(a[2]), "r"(a[3]), "r"(b[0]), "r"(b[1]));
}
__device__ __forceinline__ void ldsm4(uint32_t& r0, uint32_t& r1, uint32_t& r2, uint32_t& r3,
                                      uint32_t addr)
{
    asm volatile("ldmatrix.sync.aligned.m8n8.x4.shared.b16 {%0,%1,%2,%3}, [%4];"
                 : "=r"(r0), "=r"(r1), "=r"(r2), "=r"(r3) : "r"(addr));
}
__device__ __forceinline__ void ldsm4t(uint32_t& r0, uint32_t& r1, uint32_t& r2, uint32_t& r3,
                                       uint32_t addr)
{
    asm volatile("ldmatrix.sync.aligned.m8n8.x4.trans.shared.b16 {%0,%1,%2,%3}, [%4];"
                 : "=r"(r0), "=r"(r1), "=r"(r2), "=r"(r3) : "r"(addr));
}
__device__ __forceinline__ void cp16(uint32_t saddr, const void* g)
{
    asm volatile("cp.async.cg.shared.global [%0], [%1], 16;"
                 :: "r"(saddr), "l"(g));
}
__device__ __forceinline__ uint32_t smem_u32(const void* p) {
    uint32_t a;
    asm("{ .reg .u64 t; cvta.to.shared.u64 t, %1; cvt.u32.u64 %0, t; }"
        : "=r"(a) : "l"(p));
    return a;
}
__device__ __forceinline__ uint32_t pack2h(float f0, float f1)
{
    __half2 p = __floats2half2_rn(f0, f1);
    return *(uint32_t*)&p;
}

// ---------------- fp32 -> fp16 convert ----------------
__global__ __launch_bounds__(256)
void to_half(const float* __restrict__ x, __half* __restrict__ h, int n)
{
    int i = (blockIdx.x * 256 + threadIdx.x) * 4;
    if (i >= n) return;
    float4 v = *(const float4*)(x + i);
    __half hh[4] = {__float2half_rn(v.x), __float2half_rn(v.y),
                    __float2half_rn(v.z), __float2half_rn(v.w)};
    *(uint2*)(h + i) = *(uint2*)hh;
}

// ---------------- transpose W: W[K][N] -> T[N][K] (fp16) ----------------
__global__ __launch_bounds__(256)
void transpose_h(const float* __restrict__ W, __half* __restrict__ T, int K, int N)
{
    __shared__ float tile[32][33];
    int n0 = blockIdx.x * 32, k0 = blockIdx.y * 32;
    int tx = threadIdx.x, ty = threadIdx.y;
#pragma unroll
    for (int i = 0; i < 32; i += 8)
        tile[ty + i][tx] = W[(size_t)(k0 + ty + i) * N + n0 + tx];
    __syncthreads();
#pragma unroll
    for (int i = 0; i < 32; i += 8) {
        int n = n0 + ty + i, k = k0 + tx;
        T[(size_t)n * K + k] = __float2half_rn(tile[tx][ty + i]);
    }
}

// ---------------- fp16 single-pass GEMM: 128x128, 4 warps, 3-stage, 1 barrier/chunk ----------------
// FUSE=0: C fp32 out. FUSE=1: QKV epilogue — sec0->qh, sec1->kh, sec2->vh (fp16, stride 1024).
#define GBK      32
#define GSTRIDE  40
#define ROWB     (GSTRIDE * 2)
#define ARR_B    (128 * ROWB)              // 10240 B
#define STAGE_B  (2 * ARR_B)               // A, B  = 20480 B
#define GEMM_SMEM (3 * STAGE_B)            // 61440 B (3-stage)

template<bool FUSE>
__global__ __launch_bounds__(128, 2)
void gemm_mma(const __half* __restrict__ A, const __half* __restrict__ B,
              const float* __restrict__ bias, float* __restrict__ C, int N,
              __half* __restrict__ qh, __half* __restrict__ kh, __half* __restrict__ vh)
{
    extern __shared__ char smem[];
    const uint32_t sb = smem_u32(smem);
    const int tid  = threadIdx.x;
    const int wid  = tid >> 5, lane = tid & 31;
    const int wm   = wid >> 1, wn = wid & 1;          // warp grid 2x2, tile 64x64
    const int g    = lane >> 2, tig = lane & 3;
    const int bm   = blockIdx.y * 128, bn = blockIdx.x * 128;
    const int NC   = Kdim / GBK;

    const int qd = lane >> 3, il = lane & 7;
    const uint32_t offA = (uint32_t)((wm * 64 + il + (qd & 1) * 8) * ROWB + ((qd >> 1) * 8) * 2);
    const uint32_t offB = (uint32_t)((wn * 64 + il + (qd >> 1) * 8) * ROWB + ((qd & 1) * 8) * 2);

    float acc[4][8][4];
#pragma unroll
    for (int im = 0; im < 4; im++)
#pragma unroll
        for (int in = 0; in < 8; in++)
#pragma unroll
            for (int q = 0; q < 4; q++) acc[im][in][q] = 0.0f;

    auto prefetch = [&](int c) {
        const int st = c % 3;
#pragma unroll
        for (int i = 0; i < 8; i++) {
            int idx = tid + i * 128;        // 0..1023 16B-units
            int arr = idx >> 9;             // 0:A 1:B
            int e   = idx & 511;
            int row = e >> 2;
            int seg = e & 3;
            const __half* gp;
            size_t koff = (size_t)c * GBK + seg * 8;
            if (arr == 0) gp = A + (size_t)(bm + row) * Kdim + koff;
            else          gp = B + (size_t)(bn + row) * Kdim + koff;
            uint32_t sa = sb + st * STAGE_B + arr * ARR_B + row * ROWB + seg * 16;
            cp16(sa, gp);
        }
        asm volatile("cp.async.commit_group;");
    };

    prefetch(0);

    for (int c = 0; c < NC; c++) {
        const int st = c % 3;
        if (c + 1 < NC) {
            prefetch(c + 1);                // writes stage (c+1)%3 == (c-2)%3, reads done pre-barrier(c-1)
            asm volatile("cp.async.wait_group 1;");
        } else {
            asm volatile("cp.async.wait_group 0;");
        }
        __syncthreads();                    // single barrier per chunk

        const uint32_t stb = sb + st * STAGE_B;

#pragma unroll
        for (int kk = 0; kk < GBK; kk += 16) {
            const uint32_t kb = (uint32_t)(kk * 2);
            uint32_t a[4][4], bf[8][2];
#pragma unroll
            for (int p = 0; p < 4; p++)
                ldsm4(bf[2*p][0], bf[2*p][1], bf[2*p+1][0], bf[2*p+1][1],
                      stb + ARR_B + offB + p * (16 * ROWB) + kb);
#pragma unroll
            for (int im = 0; im < 4; im++)
                ldsm4(a[im][0], a[im][1], a[im][2], a[im][3],
                      stb + offA + im * (16 * ROWB) + kb);
#pragma unroll
            for (int im = 0; im < 4; im++)
#pragma unroll
                for (int in = 0; in < 8; in++)
                    mma16816(acc[im][in], a[im], bf[in]);
        }
    }

    // epilogue
    __half* d = qh;
    if (FUSE) {
        int sec = bn >> 10;                // uniform per CTA
        if (sec == 1) d = kh;
        else if (sec == 2) d = vh;
    }
#pragma unroll
    for (int im = 0; im < 4; im++) {
        int r = bm + wm * 64 + im * 16 + g;
#pragma unroll
        for (int in = 0; in < 8; in++) {
            int ccol = bn + wn * 64 + in * 8 + 2 * tig;
            float2 b01 = *(const float2*)&bias[ccol];
            float2 o0 = make_float2(acc[im][in][0] + b01.x, acc[im][in][1] + b01.y);
            float2 o1 = make_float2(acc[im][in][2] + b01.x, acc[im][in][3] + b01.y);
            if (!FUSE) {
                *(float2*)&C[(size_t)r * N + ccol]       = o0;
                *(float2*)&C[(size_t)(r + 8) * N + ccol] = o1;
            } else {
                int col = ccol & 1023;
                *(uint32_t*)&d[(size_t)r * 1024 + col]       = pack2h(o0.x, o0.y);
                *(uint32_t*)&d[(size_t)(r + 8) * 1024 + col] = pack2h(o1.x, o1.y);
            }
        }
    }
}

// ---------------- fp16 single-pass flash attention (R12, unchanged) ----------------
#define AKVROW 144
#define AARR   9216
#define AST    (2 * AARR)                  // 18432
#define ATTN_SMEM (3 * AST)                // 55296

__global__ __launch_bounds__(256, 1)
void attn_mma(const __half* __restrict__ qh,
              const __half* __restrict__ kh, const __half* __restrict__ vh,
              const int* __restrict__ mask, __half* __restrict__ oh)
{
    extern __shared__ char asmem[];
    __shared__ int sMask[3][64];
    const uint32_t sb = smem_u32(asmem);
    const uint32_t mb = smem_u32(&sMask[0][0]);

    const int tid = threadIdx.x, wid = tid >> 5, lane = tid & 31;
    const int g = lane >> 2, tig = lane & 3;
    const int qd = lane >> 3, il = lane & 7;
    const uint32_t offKV  = (uint32_t)((il + (qd >> 1) * 8) * AKVROW + ((qd & 1) * 8) * 2);
    const uint32_t offKVt = (uint32_t)((il + (qd & 1) * 8) * AKVROW + ((qd >> 1) * 8) * 2);

    const int qt = gridDim.x - 1 - blockIdx.x;   // heavy tiles launch first
    const int bh = blockIdx.y;
    const int b = bh >> 4, h = bh & 15;
    const int q0 = qt * 128;
    const int wrow = q0 + wid * 16;
    const float scale = 0.125f;

    uint32_t aq[4][4];
    {
        const __half* qb = qh + (size_t)(b * Ss + wrow) * Ee + h * 64;
#pragma unroll
        for (int s = 0; s < 4; s++) {
            int k0 = s * 16 + 2 * tig;
            aq[s][0] = *(const uint32_t*)&qb[(size_t)(g    ) * Ee + k0];
            aq[s][1] = *(const uint32_t*)&qb[(size_t)(g + 8) * Ee + k0];
            aq[s][2] = *(const uint32_t*)&qb[(size_t)(g    ) * Ee + k0 + 8];
            aq[s][3] = *(const uint32_t*)&qb[(size_t)(g + 8) * Ee + k0 + 8];
        }
    }

    auto prefetch = [&](int j) {
        const int kv0 = j * 64;
        const int st = j % 3;
        const uint32_t stb = sb + st * AST;
#pragma unroll
        for (int i = 0; i < 4; i++) {
            int idx = tid + i * 256;
            int arr = idx >> 9;             // 0:K 1:V
            int e   = idx & 511;
            int row = e >> 3;
            int segB = (e & 7) * 16;
            const __half* gp = (arr == 0 ? kh : vh)
                             + (size_t)(b * Ss + kv0 + row) * Ee + h * 64 + segB / 2;
            cp16(stb + arr * AARR + row * AKVROW + segB, gp);
        }
        if (tid < 16)
            cp16(mb + st * 256 + tid * 16, &mask[b * Ss + kv0 + tid * 4]);
        asm volatile("cp.async.commit_group;");
    };

    float m0 = -1e30f, m1 = -1e30f, l0 = 0.0f, l1 = 0.0f;
    float o[8][4];
#pragma unroll
    for (int t = 0; t < 8; t++)
#pragma unroll
        for (int e = 0; e < 4; e++) o[t][e] = 0.0f;

    const int row0 = wrow + g, row1 = wrow + 8 + g;
    const int ntiles = (qt + 1) * 2;

    prefetch(0);

    for (int j = 0; j < ntiles; j++) {
        const int kv0 = j * 64;
        const int st = j % 3;
        if (j + 1 < ntiles) {
            prefetch(j + 1);
            asm volatile("cp.async.wait_group 1;");
        } else {
            asm volatile("cp.async.wait_group 0;");
        }
        __syncthreads();

        const uint32_t stb = sb + st * AST;
        const int* msk = sMask[st];

        float c[8][4];
#pragma unroll
        for (int t = 0; t < 8; t++)
#pragma unroll
            for (int e = 0; e < 4; e++) c[t][e] = 0.0f;

#pragma unroll
        for (int s = 0; s < 4; s++) {
            const uint32_t kb = (uint32_t)(s * 32);
            uint32_t kf[8][2];
#pragma unroll
            for (int p = 0; p < 4; p++)
                ldsm4(kf[2*p][0], kf[2*p][1], kf[2*p+1][0], kf[2*p+1][1],
                      stb + offKV + p * (16 * AKVROW) + kb);
#pragma unroll
            for (int t = 0; t < 8; t++)
                mma16816(c[t], aq[s], kf[t]);
        }

#pragma unroll
        for (int t = 0; t < 8; t++) {
            int lc0 = t * 8 + 2 * tig;
            int col0 = kv0 + lc0, col1 = col0 + 1;
            bool v0 = msk[lc0] != 0, v1 = msk[lc0 + 1] != 0;
            c[t][0] = (v0 && col0 <= row0) ? c[t][0] * scale : -1e30f;
            c[t][1] = (v1 && col1 <= row0) ? c[t][1] * scale : -1e30f;
            c[t][2] = (v0 && col0 <= row1) ? c[t][2] * scale : -1e30f;
            c[t][3] = (v1 && col1 <= row1) ? c[t][3] * scale : -1e30f;
        }

        float ml0 = -1e30f, ml1 = -1e30f;
#pragma unroll
        for (int t = 0; t < 8; t++) {
            ml0 = fmaxf(ml0, fmaxf(c[t][0], c[t][1]));
            ml1 = fmaxf(ml1, fmaxf(c[t][2], c[t][3]));
        }
        ml0 = fmaxf(ml0, __shfl_xor_sync(0xffffffffu, ml0, 1));
        ml0 = fmaxf(ml0, __shfl_xor_sync(0xffffffffu, ml0, 2));
        ml1 = fmaxf(ml1, __shfl_xor_sync(0xffffffffu, ml1, 1));
        ml1 = fmaxf(ml1, __shfl_xor_sync(0xffffffffu, ml1, 2));

        float mn0 = fmaxf(m0, ml0), mn1 = fmaxf(m1, ml1);
        float alpha0 = __expf(m0 - mn0), alpha1 = __expf(m1 - mn1);
        m0 = mn0; m1 = mn1;

        float rs0 = 0.0f, rs1 = 0.0f;
#pragma unroll
        for (int t = 0; t < 8; t++) {
            c[t][0] = __expf(c[t][0] - m0); rs0 += c[t][0];
            c[t][1] = __expf(c[t][1] - m0); rs0 += c[t][1];
            c[t][2] = __expf(c[t][2] - m1); rs1 += c[t][2];
            c[t][3] = __expf(c[t][3] - m1); rs1 += c[t][3];
        }
        rs0 += __shfl_xor_sync(0xffffffffu, rs0, 1);
        rs0 += __shfl_xor_sync(0xffffffffu, rs0, 2);
        rs1 += __shfl_xor_sync(0xffffffffu, rs1, 1);
        rs1 += __shfl_xor_sync(0xffffffffu, rs1, 2);

        l0 = l0 * alpha0 + rs0;
        l1 = l1 * alpha1 + rs1;
#pragma unroll
        for (int t = 0; t < 8; t++) {
            o[t][0] *= alpha0; o[t][1] *= alpha0;
            o[t][2] *= alpha1; o[t][3] *= alpha1;
        }

#pragma unroll
        for (int s = 0; s < 4; s++) {
            uint32_t ap[4];
            ap[0] = pack2h(c[2 * s][0],     c[2 * s][1]);
            ap[1] = pack2h(c[2 * s][2],     c[2 * s][3]);
            ap[2] = pack2h(c[2 * s + 1][0], c[2 * s + 1][1]);
            ap[3] = pack2h(c[2 * s + 1][2], c[2 * s + 1][3]);
            const uint32_t krow = (uint32_t)(s * 16 * AKVROW);
            uint32_t vf[8][2];
#pragma unroll
            for (int p = 0; p < 4; p++)
                ldsm4t(vf[2*p][0], vf[2*p][1], vf[2*p+1][0], vf[2*p+1][1],
                       stb + AARR + offKVt + krow + p * 32);
#pragma unroll
            for (int t = 0; t < 8; t++)
                mma16816(o[t], ap, vf[t]);
        }
    }

    float inv0 = 1.0f / l0, inv1 = 1.0f / l1;
    size_t base0 = (size_t)(b * Ss + row0) * Ee + h * 64;
    size_t base1 = (size_t)(b * Ss + row1) * Ee + h * 64;
#pragma unroll
    for (int t = 0; t < 8; t++) {
        int cc = t * 8 + 2 * tig;
        *(uint32_t*)&oh[base0 + cc] = pack2h(o[t][0] * inv0, o[t][1] * inv0);
        *(uint32_t*)&oh[base1 + cc] = pack2h(o[t][2] * inv1, o[t][3] * inv1);
    }
}

// ---------------- launch ----------------
extern "C" void kernel_launch(void* const* d_in, const int* in_sizes, int n_in,
                              void* d_out, int out_size)
{
    const float* X     = (const float*)d_in[0];
    const int*   mask  = (const int*)  d_in[1];
    const float* Wqkv  = (const float*)d_in[2];
    const float* bqkv  = (const float*)d_in[3];
    const float* Wproj = (const float*)d_in[4];
    const float* bproj = (const float*)d_in[5];
    float* out = (float*)d_out;

    __half *xh, *qh, *kh, *vh, *wq, *wp, *oh;
    cudaGetSymbolAddress((void**)&xh, g_xh);
    cudaGetSymbolAddress((void**)&qh, g_qh);
    cudaGetSymbolAddress((void**)&kh, g_kh);
    cudaGetSymbolAddress((void**)&vh, g_vh);
    cudaGetSymbolAddress((void**)&wq, g_wq);
    cudaGetSymbolAddress((void**)&wp, g_wp);
    cudaGetSymbolAddress((void**)&oh, g_oh);

    cudaFuncSetAttribute(gemm_mma<true>,  cudaFuncAttributeMaxDynamicSharedMemorySize, GEMM_SMEM);
    cudaFuncSetAttribute(gemm_mma<false>, cudaFuncAttributeMaxDynamicSharedMemorySize, GEMM_SMEM);
    cudaFuncSetAttribute(attn_mma, cudaFuncAttributeMaxDynamicSharedMemorySize, ATTN_SMEM);

    // prep: X -> fp16; transpose weights -> fp16
    to_half<<<(MTOT * Ee) / 4 / 256, 256>>>(X, xh, MTOT * Ee);
    {
        dim3 blk(32, 8);
        transpose_h<<<dim3(E3 / 32, Kdim / 32), blk>>>(Wqkv, wq, Kdim, E3);
        transpose_h<<<dim3(Ee / 32, Kdim / 32), blk>>>(Wproj, wp, Kdim, Ee);
    }

    // 1) QKV = X @ Wqkv + b (fp16, 128x128 tiles, 3-stage), fused epilogue -> q/k/v fp16
    gemm_mma<true><<<dim3(E3 / 128, MTOT / 128), 128, GEMM_SMEM>>>(
        xh, wq, bqkv, nullptr, E3, qh, kh, vh);

    // 2) flash attention (fp16 single-pass)
    attn_mma<<<dim3(Ss / 128, Bb * Hh), 256, ATTN_SMEM>>>(qh, kh, vh, mask, oh);

    // 3) out = attn @ Wproj + b (fp16, fp32 out)
    gemm_mma<false><<<dim3(Ee / 128, MTOT / 128), 128, GEMM_SMEM>>>(
        oh, wp, bproj, out, Ee, qh, kh, vh);
}

// round 15
// speedup vs baseline: 1.2511x; 1.0282x over previous
#include <cuda_runtime.h>
#include <cuda_fp16.h>
#include <cstdint>
#include <math.h>

// ---------------- problem constants ----------------
#define Bb   4
#define Ss   1024
#define Ee   1024
#define Hh   16
#define HDs  64
#define MTOT 4096      // B*S
#define E3   3072      // 3*E
#define Kdim 1024

// ---------------- scratch (device globals, fp16) ----------------
__device__ __half  g_xh [MTOT * Ee];     // X fp16 (QKV GEMM A)
__device__ __half  g_qh [MTOT * Ee];     // Q fp16
__device__ __half  g_kh [MTOT * Ee];     // K fp16
__device__ __half  g_vh [MTOT * Ee];     // V fp16, row-major [s][hd]
__device__ __half  g_wq [E3 * Ee];       // Wqkv^T fp16
__device__ __half  g_wp [Ee * Ee];       // Wproj^T fp16
__device__ __half  g_oh [MTOT * Ee];     // attention output fp16 (proj A)

// ---------------- helpers ----------------
__device__ __forceinline__ void mma16816(float* c, const uint32_t* a, const uint32_t* b)
{
    asm volatile(
        "mma.sync.aligned.m16n8k16.row.col.f32.f16.f16.f32 "
        "{%0,%1,%2,%3}, {%4,%5,%6,%7}, {%8,%9}, {%0,%1,%2,%3};"
        : "+f"(c[0]), "+f"(c[1]), "+f"(c[2]), "+f"(c[3])
        : "r"(a[0]), "r"(a[1]), "r"(a[2]), "r"(a[3]), "r"(b[0]), "r"(b[1]));
}
__device__ __forceinline__ void ldsm4(uint32_t& r0, uint32_t& r1, uint32_t& r2, uint32_t& r3,
                                      uint32_t addr)
{
    asm volatile("ldmatrix.sync.aligned.m8n8.x4.shared.b16 {%0,%1,%2,%3}, [%4];"
                 : "=r"(r0), "=r"(r1), "=r"(r2), "=r"(r3) : "r"(addr));
}
__device__ __forceinline__ void ldsm4t(uint32_t& r0, uint32_t& r1, uint32_t& r2, uint32_t& r3,
                                       uint32_t addr)
{
    asm volatile("ldmatrix.sync.aligned.m8n8.x4.trans.shared.b16 {%0,%1,%2,%3}, [%4];"
                 : "=r"(r0), "=r"(r1), "=r"(r2), "=r"(r3) : "r"(addr));
}
__device__ __forceinline__ void cp16(uint32_t saddr, const void* g)
{
    asm volatile("cp.async.cg.shared.global [%0], [%1], 16;"
                 :: "r"(saddr), "l"(g));
}
__device__ __forceinline__ uint32_t smem_u32(const void* p) {
    uint32_t a;
    asm("{ .reg .u64 t; cvta.to.shared.u64 t, %1; cvt.u32.u64 %0, t; }"
        : "=r"(a) : "l"(p));
    return a;
}
__device__ __forceinline__ uint32_t pack2h(float f0, float f1)
{
    __half2 p = __floats2half2_rn(f0, f1);
    return *(uint32_t*)&p;
}

// ---------------- fp32 -> fp16 convert ----------------
__global__ __launch_bounds__(256)
void to_half(const float* __restrict__ x, __half* __restrict__ h, int n)
{
    int i = (blockIdx.x * 256 + threadIdx.x) * 4;
    if (i >= n) return;
    float4 v = *(const float4*)(x + i);
    __half hh[4] = {__float2half_rn(v.x), __float2half_rn(v.y),
                    __float2half_rn(v.z), __float2half_rn(v.w)};
    *(uint2*)(h + i) = *(uint2*)hh;
}

// ---------------- transpose W: W[K][N] -> T[N][K] (fp16) ----------------
__global__ __launch_bounds__(256)
void transpose_h(const float* __restrict__ W, __half* __restrict__ T, int K, int N)
{
    __shared__ float tile[32][33];
    int n0 = blockIdx.x * 32, k0 = blockIdx.y * 32;
    int tx = threadIdx.x, ty = threadIdx.y;
#pragma unroll
    for (int i = 0; i < 32; i += 8)
        tile[ty + i][tx] = W[(size_t)(k0 + ty + i) * N + n0 + tx];
    __syncthreads();
#pragma unroll
    for (int i = 0; i < 32; i += 8) {
        int n = n0 + ty + i, k = k0 + tx;
        T[(size_t)n * K + k] = __float2half_rn(tile[tx][ty + i]);
    }
}

// ---------------- fp16 single-pass GEMM: 128x128, 4 warps, 3-stage, 1 barrier/chunk ----------------
// FUSE=0: C fp32 out. FUSE=1: QKV epilogue — sec0->qh, sec1->kh, sec2->vh (fp16, stride 1024).
#define GBK      32
#define GSTRIDE  40
#define ROWB     (GSTRIDE * 2)
#define ARR_B    (128 * ROWB)              // 10240 B
#define STAGE_B  (2 * ARR_B)               // A, B  = 20480 B
#define GEMM_SMEM (3 * STAGE_B)            // 61440 B (3-stage)

template<bool FUSE>
__global__ __launch_bounds__(128, 2)
void gemm_mma(const __half* __restrict__ A, const __half* __restrict__ B,
              const float* __restrict__ bias, float* __restrict__ C, int N,
              __half* __restrict__ qh, __half* __restrict__ kh, __half* __restrict__ vh)
{
    extern __shared__ char smem[];
    const uint32_t sb = smem_u32(smem);
    const int tid  = threadIdx.x;
    const int wid  = tid >> 5, lane = tid & 31;
    const int wm   = wid >> 1, wn = wid & 1;          // warp grid 2x2, tile 64x64
    const int g    = lane >> 2, tig = lane & 3;
    const int bm   = blockIdx.y * 128, bn = blockIdx.x * 128;
    const int NC   = Kdim / GBK;

    const int qd = lane >> 3, il = lane & 7;
    const uint32_t offA = (uint32_t)((wm * 64 + il + (qd & 1) * 8) * ROWB + ((qd >> 1) * 8) * 2);
    const uint32_t offB = (uint32_t)((wn * 64 + il + (qd >> 1) * 8) * ROWB + ((qd & 1) * 8) * 2);

    float acc[4][8][4];
#pragma unroll
    for (int im = 0; im < 4; im++)
#pragma unroll
        for (int in = 0; in < 8; in++)
#pragma unroll
            for (int q = 0; q < 4; q++) acc[im][in][q] = 0.0f;

    auto prefetch = [&](int c) {
        const int st = c % 3;
#pragma unroll
        for (int i = 0; i < 8; i++) {
            int idx = tid + i * 128;        // 0..1023 16B-units
            int arr = idx >> 9;             // 0:A 1:B
            int e   = idx & 511;
            int row = e >> 2;
            int seg = e & 3;
            const __half* gp;
            size_t koff = (size_t)c * GBK + seg * 8;
            if (arr == 0) gp = A + (size_t)(bm + row) * Kdim + koff;
            else          gp = B + (size_t)(bn + row) * Kdim + koff;
            uint32_t sa = sb + st * STAGE_B + arr * ARR_B + row * ROWB + seg * 16;
            cp16(sa, gp);
        }
        asm volatile("cp.async.commit_group;");
    };

    prefetch(0);

    for (int c = 0; c < NC; c++) {
        const int st = c % 3;
        if (c + 1 < NC) {
            prefetch(c + 1);
            asm volatile("cp.async.wait_group 1;");
        } else {
            asm volatile("cp.async.wait_group 0;");
        }
        __syncthreads();                    // single barrier per chunk

        const uint32_t stb = sb + st * STAGE_B;

#pragma unroll
        for (int kk = 0; kk < GBK; kk += 16) {
            const uint32_t kb = (uint32_t)(kk * 2);
            uint32_t a[4][4], bf[8][2];
#pragma unroll
            for (int p = 0; p < 4; p++)
                ldsm4(bf[2*p][0], bf[2*p][1], bf[2*p+1][0], bf[2*p+1][1],
                      stb + ARR_B + offB + p * (16 * ROWB) + kb);
#pragma unroll
            for (int im = 0; im < 4; im++)
                ldsm4(a[im][0], a[im][1], a[im][2], a[im][3],
                      stb + offA + im * (16 * ROWB) + kb);
#pragma unroll
            for (int im = 0; im < 4; im++)
#pragma unroll
                for (int in = 0; in < 8; in++)
                    mma16816(acc[im][in], a[im], bf[in]);
        }
    }

    // epilogue
    __half* d = qh;
    if (FUSE) {
        int sec = bn >> 10;                // uniform per CTA
        if (sec == 1) d = kh;
        else if (sec == 2) d = vh;
    }
#pragma unroll
    for (int im = 0; im < 4; im++) {
        int r = bm + wm * 64 + im * 16 + g;
#pragma unroll
        for (int in = 0; in < 8; in++) {
            int ccol = bn + wn * 64 + in * 8 + 2 * tig;
            float2 b01 = *(const float2*)&bias[ccol];
            float2 o0 = make_float2(acc[im][in][0] + b01.x, acc[im][in][1] + b01.y);
            float2 o1 = make_float2(acc[im][in][2] + b01.x, acc[im][in][3] + b01.y);
            if (!FUSE) {
                *(float2*)&C[(size_t)r * N + ccol]       = o0;
                *(float2*)&C[(size_t)(r + 8) * N + ccol] = o1;
            } else {
                int col = ccol & 1023;
                *(uint32_t*)&d[(size_t)r * 1024 + col]       = pack2h(o0.x, o0.y);
                *(uint32_t*)&d[(size_t)(r + 8) * 1024 + col] = pack2h(o1.x, o1.y);
            }
        }
    }
}

// ---------------- fp16 single-pass flash attention: 2 CTAs/SM ----------------
#define AKVROW 144
#define AARR   9216
#define AST    (2 * AARR)                  // 18432
#define ATTN_SMEM (3 * AST)                // 55296 (x2 CTAs = 110.6 KB/SM)

__global__ __launch_bounds__(256, 2)
void attn_mma(const __half* __restrict__ qh,
              const __half* __restrict__ kh, const __half* __restrict__ vh,
              const int* __restrict__ mask, __half* __restrict__ oh)
{
    extern __shared__ char asmem[];
    __shared__ int sMask[3][64];
    const uint32_t sb = smem_u32(asmem);
    const uint32_t mb = smem_u32(&sMask[0][0]);

    const int tid = threadIdx.x, wid = tid >> 5, lane = tid & 31;
    const int g = lane >> 2, tig = lane & 3;
    const int qd = lane >> 3, il = lane & 7;
    const uint32_t offKV  = (uint32_t)((il + (qd >> 1) * 8) * AKVROW + ((qd & 1) * 8) * 2);
    const uint32_t offKVt = (uint32_t)((il + (qd & 1) * 8) * AKVROW + ((qd >> 1) * 8) * 2);

    const int qt = gridDim.x - 1 - blockIdx.x;   // heavy tiles launch first
    const int bh = blockIdx.y;
    const int b = bh >> 4, h = bh & 15;
    const int q0 = qt * 128;
    const int wrow = q0 + wid * 16;
    const float scale = 0.125f;

    uint32_t aq[4][4];
    {
        const __half* qb = qh + (size_t)(b * Ss + wrow) * Ee + h * 64;
#pragma unroll
        for (int s = 0; s < 4; s++) {
            int k0 = s * 16 + 2 * tig;
            aq[s][0] = *(const uint32_t*)&qb[(size_t)(g    ) * Ee + k0];
            aq[s][1] = *(const uint32_t*)&qb[(size_t)(g + 8) * Ee + k0];
            aq[s][2] = *(const uint32_t*)&qb[(size_t)(g    ) * Ee + k0 + 8];
            aq[s][3] = *(const uint32_t*)&qb[(size_t)(g + 8) * Ee + k0 + 8];
        }
    }

    auto prefetch = [&](int j) {
        const int kv0 = j * 64;
        const int st = j % 3;
        const uint32_t stb = sb + st * AST;
#pragma unroll
        for (int i = 0; i < 4; i++) {
            int idx = tid + i * 256;
            int arr = idx >> 9;             // 0:K 1:V
            int e   = idx & 511;
            int row = e >> 3;
            int segB = (e & 7) * 16;
            const __half* gp = (arr == 0 ? kh : vh)
                             + (size_t)(b * Ss + kv0 + row) * Ee + h * 64 + segB / 2;
            cp16(stb + arr * AARR + row * AKVROW + segB, gp);
        }
        if (tid < 16)
            cp16(mb + st * 256 + tid * 16, &mask[b * Ss + kv0 + tid * 4]);
        asm volatile("cp.async.commit_group;");
    };

    float m0 = -1e30f, m1 = -1e30f, l0 = 0.0f, l1 = 0.0f;
    float o[8][4];
#pragma unroll
    for (int t = 0; t < 8; t++)
#pragma unroll
        for (int e = 0; e < 4; e++) o[t][e] = 0.0f;

    const int row0 = wrow + g, row1 = wrow + 8 + g;
    const int ntiles = (qt + 1) * 2;

    prefetch(0);

    for (int j = 0; j < ntiles; j++) {
        const int kv0 = j * 64;
        const int st = j % 3;
        if (j + 1 < ntiles) {
            prefetch(j + 1);
            asm volatile("cp.async.wait_group 1;");
        } else {
            asm volatile("cp.async.wait_group 0;");
        }
        __syncthreads();

        const uint32_t stb = sb + st * AST;
        const int* msk = sMask[st];

        float c[8][4];
#pragma unroll
        for (int t = 0; t < 8; t++)
#pragma unroll
            for (int e = 0; e < 4; e++) c[t][e] = 0.0f;

#pragma unroll
        for (int s = 0; s < 4; s++) {
            const uint32_t kb = (uint32_t)(s * 32);
            uint32_t kf[8][2];
#pragma unroll
            for (int p = 0; p < 4; p++)
                ldsm4(kf[2*p][0], kf[2*p][1], kf[2*p+1][0], kf[2*p+1][1],
                      stb + offKV + p * (16 * AKVROW) + kb);
#pragma unroll
            for (int t = 0; t < 8; t++)
                mma16816(c[t], aq[s], kf[t]);
        }

#pragma unroll
        for (int t = 0; t < 8; t++) {
            int lc0 = t * 8 + 2 * tig;
            int col0 = kv0 + lc0, col1 = col0 + 1;
            bool v0 = msk[lc0] != 0, v1 = msk[lc0 + 1] != 0;
            c[t][0] = (v0 && col0 <= row0) ? c[t][0] * scale : -1e30f;
            c[t][1] = (v1 && col1 <= row0) ? c[t][1] * scale : -1e30f;
            c[t][2] = (v0 && col0 <= row1) ? c[t][2] * scale : -1e30f;
            c[t][3] = (v1 && col1 <= row1) ? c[t][3] * scale : -1e30f;
        }

        float ml0 = -1e30f, ml1 = -1e30f;
#pragma unroll
        for (int t = 0; t < 8; t++) {
            ml0 = fmaxf(ml0, fmaxf(c[t][0], c[t][1]));
            ml1 = fmaxf(ml1, fmaxf(c[t][2], c[t][3]));
        }
        ml0 = fmaxf(ml0, __shfl_xor_sync(0xffffffffu, ml0, 1));
        ml0 = fmaxf(ml0, __shfl_xor_sync(0xffffffffu, ml0, 2));
        ml1 = fmaxf(ml1, __shfl_xor_sync(0xffffffffu, ml1, 1));
        ml1 = fmaxf(ml1, __shfl_xor_sync(0xffffffffu, ml1, 2));

        float mn0 = fmaxf(m0, ml0), mn1 = fmaxf(m1, ml1);
        float alpha0 = __expf(m0 - mn0), alpha1 = __expf(m1 - mn1);
        m0 = mn0; m1 = mn1;

        float rs0 = 0.0f, rs1 = 0.0f;
#pragma unroll
        for (int t = 0; t < 8; t++) {
            c[t][0] = __expf(c[t][0] - m0); rs0 += c[t][0];
            c[t][1] = __expf(c[t][1] - m0); rs0 += c[t][1];
            c[t][2] = __expf(c[t][2] - m1); rs1 += c[t][2];
            c[t][3] = __expf(c[t][3] - m1); rs1 += c[t][3];
        }
        rs0 += __shfl_xor_sync(0xffffffffu, rs0, 1);
        rs0 += __shfl_xor_sync(0xffffffffu, rs0, 2);
        rs1 += __shfl_xor_sync(0xffffffffu, rs1, 1);
        rs1 += __shfl_xor_sync(0xffffffffu, rs1, 2);

        l0 = l0 * alpha0 + rs0;
        l1 = l1 * alpha1 + rs1;
#pragma unroll
        for (int t = 0; t < 8; t++) {
            o[t][0] *= alpha0; o[t][1] *= alpha0;
            o[t][2] *= alpha1; o[t][3] *= alpha1;
        }

#pragma unroll
        for (int s = 0; s < 4; s++) {
            uint32_t ap[4];
            ap[0] = pack2h(c[2 * s][0],     c[2 * s][1]);
            ap[1] = pack2h(c[2 * s][2],     c[2 * s][3]);
            ap[2] = pack2h(c[2 * s + 1][0], c[2 * s + 1][1]);
            ap[3] = pack2h(c[2 * s + 1][2], c[2 * s + 1][3]);
            const uint32_t krow = (uint32_t)(s * 16 * AKVROW);
            uint32_t vf[8][2];
#pragma unroll
            for (int p = 0; p < 4; p++)
                ldsm4t(vf[2*p][0], vf[2*p][1], vf[2*p+1][0], vf[2*p+1][1],
                       stb + AARR + offKVt + krow + p * 32);
#pragma unroll
            for (int t = 0; t < 8; t++)
                mma16816(o[t], ap, vf[t]);
        }
    }

    float inv0 = 1.0f / l0, inv1 = 1.0f / l1;
    size_t base0 = (size_t)(b * Ss + row0) * Ee + h * 64;
    size_t base1 = (size_t)(b * Ss + row1) * Ee + h * 64;
#pragma unroll
    for (int t = 0; t < 8; t++) {
        int cc = t * 8 + 2 * tig;
        *(uint32_t*)&oh[base0 + cc] = pack2h(o[t][0] * inv0, o[t][1] * inv0);
        *(uint32_t*)&oh[base1 + cc] = pack2h(o[t][2] * inv1, o[t][3] * inv1);
    }
}

// ---------------- launch ----------------
extern "C" void kernel_launch(void* const* d_in, const int* in_sizes, int n_in,
                              void* d_out, int out_size)
{
    const float* X     = (const float*)d_in[0];
    const int*   mask  = (const int*)  d_in[1];
    const float* Wqkv  = (const float*)d_in[2];
    const float* bqkv  = (const float*)d_in[3];
    const float* Wproj = (const float*)d_in[4];
    const float* bproj = (const float*)d_in[5];
    float* out = (float*)d_out;

    __half *xh, *qh, *kh, *vh, *wq, *wp, *oh;
    cudaGetSymbolAddress((void**)&xh, g_xh);
    cudaGetSymbolAddress((void**)&qh, g_qh);
    cudaGetSymbolAddress((void**)&kh, g_kh);
    cudaGetSymbolAddress((void**)&vh, g_vh);
    cudaGetSymbolAddress((void**)&wq, g_wq);
    cudaGetSymbolAddress((void**)&wp, g_wp);
    cudaGetSymbolAddress((void**)&oh, g_oh);

    cudaFuncSetAttribute(gemm_mma<true>,  cudaFuncAttributeMaxDynamicSharedMemorySize, GEMM_SMEM);
    cudaFuncSetAttribute(gemm_mma<false>, cudaFuncAttributeMaxDynamicSharedMemorySize, GEMM_SMEM);
    cudaFuncSetAttribute(attn_mma, cudaFuncAttributeMaxDynamicSharedMemorySize, ATTN_SMEM);

    // prep: X -> fp16; transpose weights -> fp16
    to_half<<<(MTOT * Ee) / 4 / 256, 256>>>(X, xh, MTOT * Ee);
    {
        dim3 blk(32, 8);
        transpose_h<<<dim3(E3 / 32, Kdim / 32), blk>>>(Wqkv, wq, Kdim, E3);
        transpose_h<<<dim3(Ee / 32, Kdim / 32), blk>>>(Wproj, wp, Kdim, Ee);
    }

    // 1) QKV = X @ Wqkv + b (fp16, 128x128 tiles, 3-stage), fused epilogue -> q/k/v fp16
    gemm_mma<true><<<dim3(E3 / 128, MTOT / 128), 128, GEMM_SMEM>>>(
        xh, wq, bqkv, nullptr, E3, qh, kh, vh);

    // 2) flash attention (fp16 single-pass, 2 CTAs/SM)
    attn_mma<<<dim3(Ss / 128, Bb * Hh), 256, ATTN_SMEM>>>(qh, kh, vh, mask, oh);

    // 3) out = attn @ Wproj + b (fp16, fp32 out)
    gemm_mma<false><<<dim3(Ee / 128, MTOT / 128), 128, GEMM_SMEM>>>(
        oh, wp, bproj, out, Ee, qh, kh, vh);
}

// round 16
// speedup vs baseline: 1.3000x; 1.0391x over previous
#include <cuda_runtime.h>
#include <cuda_fp16.h>
#include <cstdint>
#include <math.h>

// ---------------- problem constants ----------------
#define Bb   4
#define Ss   1024
#define Ee   1024
#define Hh   16
#define HDs  64
#define MTOT 4096      // B*S
#define E3   3072      // 3*E
#define Kdim 1024

#define NX   (MTOT * Ee)    // 4194304
#define NWQ  (Kdim * E3)    // 3145728
#define NWP  (Kdim * Ee)    // 1048576

// ---------------- scratch (device globals, fp16) ----------------
__device__ __half  g_xh [NX];            // X fp16 (QKV GEMM A)
__device__ __half  g_qh [NX];            // Q fp16
__device__ __half  g_kh [NX];            // K fp16
__device__ __half  g_vh [NX];            // V fp16, row-major [s][hd]
__device__ __half  g_wq [NWQ];           // Wqkv fp16, K-major [K][3E]
__device__ __half  g_wp [NWP];           // Wproj fp16, K-major [K][E]
__device__ __half  g_oh [NX];            // attention output fp16 (proj A)

// ---------------- helpers ----------------
__device__ __forceinline__ void mma16816(float* c, const uint32_t* a, const uint32_t* b)
{
    asm volatile(
        "mma.sync.aligned.m16n8k16.row.col.f32.f16.f16.f32 "
        "{%0,%1,%2,%3}, {%4,%5,%6,%7}, {%8,%9}, {%0,%1,%2,%3};"
        : "+f"(c[0]), "+f"(c[1]), "+f"(c[2]), "+f"(c[3])
        : "r"(a[0]), "r"(a[1]), "r"(a[2]), "r"(a[3]), "r"(b[0]), "r"(b[1]));
}
__device__ __forceinline__ void ldsm4(uint32_t& r0, uint32_t& r1, uint32_t& r2, uint32_t& r3,
                                      uint32_t addr)
{
    asm volatile("ldmatrix.sync.aligned.m8n8.x4.shared.b16 {%0,%1,%2,%3}, [%4];"
                 : "=r"(r0), "=r"(r1), "=r"(r2), "=r"(r3) : "r"(addr));
}
__device__ __forceinline__ void ldsm4t(uint32_t& r0, uint32_t& r1, uint32_t& r2, uint32_t& r3,
                                       uint32_t addr)
{
    asm volatile("ldmatrix.sync.aligned.m8n8.x4.trans.shared.b16 {%0,%1,%2,%3}, [%4];"
                 : "=r"(r0), "=r"(r1), "=r"(r2), "=r"(r3) : "r"(addr));
}
__device__ __forceinline__ void cp16(uint32_t saddr, const void* g)
{
    asm volatile("cp.async.cg.shared.global [%0], [%1], 16;"
                 :: "r"(saddr), "l"(g));
}
__device__ __forceinline__ uint32_t smem_u32(const void* p) {
    uint32_t a;
    asm("{ .reg .u64 t; cvta.to.shared.u64 t, %1; cvt.u32.u64 %0, t; }"
        : "=r"(a) : "l"(p));
    return a;
}
__device__ __forceinline__ uint32_t pack2h(float f0, float f1)
{
    __half2 p = __floats2half2_rn(f0, f1);
    return *(uint32_t*)&p;
}

// ---------------- fused prep: all fp32 -> fp16 converts in one kernel ----------------
__global__ __launch_bounds__(256)
void prep_all(const float* __restrict__ X, const float* __restrict__ Wq,
              const float* __restrict__ Wp,
              __half* __restrict__ xh, __half* __restrict__ wq, __half* __restrict__ wp)
{
    int i4 = (blockIdx.x * 256 + threadIdx.x) * 4;
    const float* src;
    __half* dst;
    int off;
    if (i4 < NX)            { src = X;  dst = xh; off = i4; }
    else if (i4 < NX + NWQ) { src = Wq; dst = wq; off = i4 - NX; }
    else                    { src = Wp; dst = wp; off = i4 - NX - NWQ; }
    float4 v = *(const float4*)(src + off);
    __half hh[4] = {__float2half_rn(v.x), __float2half_rn(v.y),
                    __float2half_rn(v.z), __float2half_rn(v.w)};
    *(uint2*)(dst + off) = *(uint2*)hh;
}

// ---------------- fp16 GEMM: 128x128, 4 warps, 3-stage, K-major B via ldsm.trans ----------------
// FUSE=0: C fp32 out. FUSE=1: QKV epilogue — sec0->qh, sec1->kh, sec2->vh (fp16, stride 1024).
#define GBK      32
#define GSTRIDE  40
#define ROWB     (GSTRIDE * 2)             // A row: 80 B
#define ARR_A    (128 * ROWB)              // 10240 B
#define BROWB    272                       // B row: 128 fp16 + 8 pad = 272 B
#define ARR_B2   (GBK * BROWB)             // 8704 B
#define STAGE_B  (ARR_A + ARR_B2)          // 18944 B
#define GEMM_SMEM (3 * STAGE_B)            // 56832 B (3-stage, 2 CTAs/SM)

template<bool FUSE>
__global__ __launch_bounds__(128, 2)
void gemm_mma(const __half* __restrict__ A, const __half* __restrict__ B,
              const float* __restrict__ bias, float* __restrict__ C, int N,
              __half* __restrict__ qh, __half* __restrict__ kh, __half* __restrict__ vh)
{
    extern __shared__ char smem[];
    const uint32_t sb = smem_u32(smem);
    const int tid  = threadIdx.x;
    const int wid  = tid >> 5, lane = tid & 31;
    const int wm   = wid >> 1, wn = wid & 1;          // warp grid 2x2, tile 64x64
    const int g    = lane >> 2, tig = lane & 3;
    const int bm   = blockIdx.y * 128, bn = blockIdx.x * 128;
    const int NC   = Kdim / GBK;

    const int qd = lane >> 3, il = lane & 7;
    // A (non-trans, [m][k])
    const uint32_t offA  = (uint32_t)((wm * 64 + il + (qd & 1) * 8) * ROWB + ((qd >> 1) * 8) * 2);
    // B (trans, smem [k][n]): k-rows via (qd&1), n-cols via (qd>>1) — same mapping as V (verified)
    const uint32_t offBt = (uint32_t)((il + (qd & 1) * 8) * BROWB + (wn * 64 + (qd >> 1) * 8) * 2);

    float acc[4][8][4];
#pragma unroll
    for (int im = 0; im < 4; im++)
#pragma unroll
        for (int in = 0; in < 8; in++)
#pragma unroll
            for (int q = 0; q < 4; q++) acc[im][in][q] = 0.0f;

    auto prefetch = [&](int c) {
        const int st = c % 3;
#pragma unroll
        for (int i = 0; i < 8; i++) {
            int idx = tid + i * 128;        // 0..1023 16B-units (A:512, B:512)
            const __half* gp;
            uint32_t sa;
            if (idx < 512) {                // A: 128 rows x 64 B
                int row = idx >> 2, seg = idx & 3;
                gp = A + (size_t)(bm + row) * Kdim + (size_t)c * GBK + seg * 8;
                sa = sb + st * STAGE_B + row * ROWB + seg * 16;
            } else {                        // B: 32 k-rows x 256 B (K-major)
                int e = idx - 512;
                int krow = e >> 4, u = e & 15;
                gp = B + (size_t)(c * GBK + krow) * N + bn + u * 8;
                sa = sb + st * STAGE_B + ARR_A + krow * BROWB + u * 16;
            }
            cp16(sa, gp);
        }
        asm volatile("cp.async.commit_group;");
    };

    prefetch(0);

    for (int c = 0; c < NC; c++) {
        const int st = c % 3;
        if (c + 1 < NC) {
            prefetch(c + 1);
            asm volatile("cp.async.wait_group 1;");
        } else {
            asm volatile("cp.async.wait_group 0;");
        }
        __syncthreads();                    // single barrier per chunk

        const uint32_t stb = sb + st * STAGE_B;

        // full-chunk fragment preload (both k-slices), then all MMAs
        uint32_t a[2][4][4], bf[2][8][2];
#pragma unroll
        for (int s2 = 0; s2 < 2; s2++) {
            const uint32_t kbA = (uint32_t)(s2 * 32);            // 16 halves = 32 B
            const uint32_t kbB = (uint32_t)(s2 * 16 * BROWB);    // 16 k-rows
#pragma unroll
            for (int p = 0; p < 4; p++)
                ldsm4t(bf[s2][2*p][0], bf[s2][2*p][1], bf[s2][2*p+1][0], bf[s2][2*p+1][1],
                       stb + ARR_A + offBt + kbB + p * 32);
#pragma unroll
            for (int im = 0; im < 4; im++)
                ldsm4(a[s2][im][0], a[s2][im][1], a[s2][im][2], a[s2][im][3],
                      stb + offA + im * (16 * ROWB) + kbA);
        }
#pragma unroll
        for (int s2 = 0; s2 < 2; s2++)
#pragma unroll
            for (int im = 0; im < 4; im++)
#pragma unroll
                for (int in = 0; in < 8; in++)
                    mma16816(acc[im][in], a[s2][im], bf[s2][in]);
    }

    // epilogue
    __half* d = qh;
    if (FUSE) {
        int sec = bn >> 10;                // uniform per CTA
        if (sec == 1) d = kh;
        else if (sec == 2) d = vh;
    }
#pragma unroll
    for (int im = 0; im < 4; im++) {
        int r = bm + wm * 64 + im * 16 + g;
#pragma unroll
        for (int in = 0; in < 8; in++) {
            int ccol = bn + wn * 64 + in * 8 + 2 * tig;
            float2 b01 = *(const float2*)&bias[ccol];
            float2 o0 = make_float2(acc[im][in][0] + b01.x, acc[im][in][1] + b01.y);
            float2 o1 = make_float2(acc[im][in][2] + b01.x, acc[im][in][3] + b01.y);
            if (!FUSE) {
                *(float2*)&C[(size_t)r * N + ccol]       = o0;
                *(float2*)&C[(size_t)(r + 8) * N + ccol] = o1;
            } else {
                int col = ccol & 1023;
                *(uint32_t*)&d[(size_t)r * 1024 + col]       = pack2h(o0.x, o0.y);
                *(uint32_t*)&d[(size_t)(r + 8) * 1024 + col] = pack2h(o1.x, o1.y);
            }
        }
    }
}

// ---------------- fp16 single-pass flash attention: 2 CTAs/SM (R15, unchanged) ----------------
#define AKVROW 144
#define AARR   9216
#define AST    (2 * AARR)                  // 18432
#define ATTN_SMEM (3 * AST)                // 55296 (x2 CTAs = 110.6 KB/SM)

__global__ __launch_bounds__(256, 2)
void attn_mma(const __half* __restrict__ qh,
              const __half* __restrict__ kh, const __half* __restrict__ vh,
              const int* __restrict__ mask, __half* __restrict__ oh)
{
    extern __shared__ char asmem[];
    __shared__ int sMask[3][64];
    const uint32_t sb = smem_u32(asmem);
    const uint32_t mb = smem_u32(&sMask[0][0]);

    const int tid = threadIdx.x, wid = tid >> 5, lane = tid & 31;
    const int g = lane >> 2, tig = lane & 3;
    const int qd = lane >> 3, il = lane & 7;
    const uint32_t offKV  = (uint32_t)((il + (qd >> 1) * 8) * AKVROW + ((qd & 1) * 8) * 2);
    const uint32_t offKVt = (uint32_t)((il + (qd & 1) * 8) * AKVROW + ((qd >> 1) * 8) * 2);

    const int qt = gridDim.x - 1 - blockIdx.x;   // heavy tiles launch first
    const int bh = blockIdx.y;
    const int b = bh >> 4, h = bh & 15;
    const int q0 = qt * 128;
    const int wrow = q0 + wid * 16;
    const float scale = 0.125f;

    uint32_t aq[4][4];
    {
        const __half* qb = qh + (size_t)(b * Ss + wrow) * Ee + h * 64;
#pragma unroll
        for (int s = 0; s < 4; s++) {
            int k0 = s * 16 + 2 * tig;
            aq[s][0] = *(const uint32_t*)&qb[(size_t)(g    ) * Ee + k0];
            aq[s][1] = *(const uint32_t*)&qb[(size_t)(g + 8) * Ee + k0];
            aq[s][2] = *(const uint32_t*)&qb[(size_t)(g    ) * Ee + k0 + 8];
            aq[s][3] = *(const uint32_t*)&qb[(size_t)(g + 8) * Ee + k0 + 8];
        }
    }

    auto prefetch = [&](int j) {
        const int kv0 = j * 64;
        const int st = j % 3;
        const uint32_t stb = sb + st * AST;
#pragma unroll
        for (int i = 0; i < 4; i++) {
            int idx = tid + i * 256;
            int arr = idx >> 9;             // 0:K 1:V
            int e   = idx & 511;
            int row = e >> 3;
            int segB = (e & 7) * 16;
            const __half* gp = (arr == 0 ? kh : vh)
                             + (size_t)(b * Ss + kv0 + row) * Ee + h * 64 + segB / 2;
            cp16(stb + arr * AARR + row * AKVROW + segB, gp);
        }
        if (tid < 16)
            cp16(mb + st * 256 + tid * 16, &mask[b * Ss + kv0 + tid * 4]);
        asm volatile("cp.async.commit_group;");
    };

    float m0 = -1e30f, m1 = -1e30f, l0 = 0.0f, l1 = 0.0f;
    float o[8][4];
#pragma unroll
    for (int t = 0; t < 8; t++)
#pragma unroll
        for (int e = 0; e < 4; e++) o[t][e] = 0.0f;

    const int row0 = wrow + g, row1 = wrow + 8 + g;
    const int ntiles = (qt + 1) * 2;

    prefetch(0);

    for (int j = 0; j < ntiles; j++) {
        const int kv0 = j * 64;
        const int st = j % 3;
        if (j + 1 < ntiles) {
            prefetch(j + 1);
            asm volatile("cp.async.wait_group 1;");
        } else {
            asm volatile("cp.async.wait_group 0;");
        }
        __syncthreads();

        const uint32_t stb = sb + st * AST;
        const int* msk = sMask[st];

        float c[8][4];
#pragma unroll
        for (int t = 0; t < 8; t++)
#pragma unroll
            for (int e = 0; e < 4; e++) c[t][e] = 0.0f;

#pragma unroll
        for (int s = 0; s < 4; s++) {
            const uint32_t kb = (uint32_t)(s * 32);
            uint32_t kf[8][2];
#pragma unroll
            for (int p = 0; p < 4; p++)
                ldsm4(kf[2*p][0], kf[2*p][1], kf[2*p+1][0], kf[2*p+1][1],
                      stb + offKV + p * (16 * AKVROW) + kb);
#pragma unroll
            for (int t = 0; t < 8; t++)
                mma16816(c[t], aq[s], kf[t]);
        }

#pragma unroll
        for (int t = 0; t < 8; t++) {
            int lc0 = t * 8 + 2 * tig;
            int col0 = kv0 + lc0, col1 = col0 + 1;
            bool v0 = msk[lc0] != 0, v1 = msk[lc0 + 1] != 0;
            c[t][0] = (v0 && col0 <= row0) ? c[t][0] * scale : -1e30f;
            c[t][1] = (v1 && col1 <= row0) ? c[t][1] * scale : -1e30f;
            c[t][2] = (v0 && col0 <= row1) ? c[t][2] * scale : -1e30f;
            c[t][3] = (v1 && col1 <= row1) ? c[t][3] * scale : -1e30f;
        }

        float ml0 = -1e30f, ml1 = -1e30f;
#pragma unroll
        for (int t = 0; t < 8; t++) {
            ml0 = fmaxf(ml0, fmaxf(c[t][0], c[t][1]));
            ml1 = fmaxf(ml1, fmaxf(c[t][2], c[t][3]));
        }
        ml0 = fmaxf(ml0, __shfl_xor_sync(0xffffffffu, ml0, 1));
        ml0 = fmaxf(ml0, __shfl_xor_sync(0xffffffffu, ml0, 2));
        ml1 = fmaxf(ml1, __shfl_xor_sync(0xffffffffu, ml1, 1));
        ml1 = fmaxf(ml1, __shfl_xor_sync(0xffffffffu, ml1, 2));

        float mn0 = fmaxf(m0, ml0), mn1 = fmaxf(m1, ml1);
        float alpha0 = __expf(m0 - mn0), alpha1 = __expf(m1 - mn1);
        m0 = mn0; m1 = mn1;

        float rs0 = 0.0f, rs1 = 0.0f;
#pragma unroll
        for (int t = 0; t < 8; t++) {
            c[t][0] = __expf(c[t][0] - m0); rs0 += c[t][0];
            c[t][1] = __expf(c[t][1] - m0); rs0 += c[t][1];
            c[t][2] = __expf(c[t][2] - m1); rs1 += c[t][2];
            c[t][3] = __expf(c[t][3] - m1); rs1 += c[t][3];
        }
        rs0 += __shfl_xor_sync(0xffffffffu, rs0, 1);
        rs0 += __shfl_xor_sync(0xffffffffu, rs0, 2);
        rs1 += __shfl_xor_sync(0xffffffffu, rs1, 1);
        rs1 += __shfl_xor_sync(0xffffffffu, rs1, 2);

        l0 = l0 * alpha0 + rs0;
        l1 = l1 * alpha1 + rs1;
#pragma unroll
        for (int t = 0; t < 8; t++) {
            o[t][0] *= alpha0; o[t][1] *= alpha0;
            o[t][2] *= alpha1; o[t][3] *= alpha1;
        }

#pragma unroll
        for (int s = 0; s < 4; s++) {
            uint32_t ap[4];
            ap[0] = pack2h(c[2 * s][0],     c[2 * s][1]);
            ap[1] = pack2h(c[2 * s][2],     c[2 * s][3]);
            ap[2] = pack2h(c[2 * s + 1][0], c[2 * s + 1][1]);
            ap[3] = pack2h(c[2 * s + 1][2], c[2 * s + 1][3]);
            const uint32_t krow = (uint32_t)(s * 16 * AKVROW);
            uint32_t vf[8][2];
#pragma unroll
            for (int p = 0; p < 4; p++)
                ldsm4t(vf[2*p][0], vf[2*p][1], vf[2*p+1][0], vf[2*p+1][1],
                       stb + AARR + offKVt + krow + p * 32);
#pragma unroll
            for (int t = 0; t < 8; t++)
                mma16816(o[t], ap, vf[t]);
        }
    }

    float inv0 = 1.0f / l0, inv1 = 1.0f / l1;
    size_t base0 = (size_t)(b * Ss + row0) * Ee + h * 64;
    size_t base1 = (size_t)(b * Ss + row1) * Ee + h * 64;
#pragma unroll
    for (int t = 0; t < 8; t++) {
        int cc = t * 8 + 2 * tig;
        *(uint32_t*)&oh[base0 + cc] = pack2h(o[t][0] * inv0, o[t][1] * inv0);
        *(uint32_t*)&oh[base1 + cc] = pack2h(o[t][2] * inv1, o[t][3] * inv1);
    }
}

// ---------------- launch ----------------
extern "C" void kernel_launch(void* const* d_in, const int* in_sizes, int n_in,
                              void* d_out, int out_size)
{
    const float* X     = (const float*)d_in[0];
    const int*   mask  = (const int*)  d_in[1];
    const float* Wqkv  = (const float*)d_in[2];
    const float* bqkv  = (const float*)d_in[3];
    const float* Wproj = (const float*)d_in[4];
    const float* bproj = (const float*)d_in[5];
    float* out = (float*)d_out;

    __half *xh, *qh, *kh, *vh, *wq, *wp, *oh;
    cudaGetSymbolAddress((void**)&xh, g_xh);
    cudaGetSymbolAddress((void**)&qh, g_qh);
    cudaGetSymbolAddress((void**)&kh, g_kh);
    cudaGetSymbolAddress((void**)&vh, g_vh);
    cudaGetSymbolAddress((void**)&wq, g_wq);
    cudaGetSymbolAddress((void**)&wp, g_wp);
    cudaGetSymbolAddress((void**)&oh, g_oh);

    cudaFuncSetAttribute(gemm_mma<true>,  cudaFuncAttributeMaxDynamicSharedMemorySize, GEMM_SMEM);
    cudaFuncSetAttribute(gemm_mma<false>, cudaFuncAttributeMaxDynamicSharedMemorySize, GEMM_SMEM);
    cudaFuncSetAttribute(attn_mma, cudaFuncAttributeMaxDynamicSharedMemorySize, ATTN_SMEM);

    // prep: all converts in ONE kernel (no transposes — B is consumed K-major via ldsm.trans)
    prep_all<<<(NX + NWQ + NWP) / 4 / 256, 256>>>(X, Wqkv, Wproj, xh, wq, wp);

    // 1) QKV = X @ Wqkv + b (fp16), fused epilogue -> q/k/v fp16
    gemm_mma<true><<<dim3(E3 / 128, MTOT / 128), 128, GEMM_SMEM>>>(
        xh, wq, bqkv, nullptr, E3, qh, kh, vh);

    // 2) flash attention (fp16 single-pass, 2 CTAs/SM)
    attn_mma<<<dim3(Ss / 128, Bb * Hh), 256, ATTN_SMEM>>>(qh, kh, vh, mask, oh);

    // 3) out = attn @ Wproj + b (fp16, fp32 out)
    gemm_mma<false><<<dim3(Ee / 128, MTOT / 128), 128, GEMM_SMEM>>>(
        oh, wp, bproj, out, Ee, qh, kh, vh);
}

// round 17
// speedup vs baseline: 1.3483x; 1.0371x over previous
#include <cuda_runtime.h>
#include <cuda_fp16.h>
#include <cstdint>
#include <math.h>

// ---------------- problem constants ----------------
#define Bb   4
#define Ss   1024
#define Ee   1024
#define Hh   16
#define HDs  64
#define MTOT 4096      // B*S
#define E3   3072      // 3*E
#define Kdim 1024

#define NX   (MTOT * Ee)    // 4194304
#define NWQ  (Kdim * E3)    // 3145728
#define NWP  (Kdim * Ee)    // 1048576

// ---------------- scratch (device globals, fp16) ----------------
__device__ __half  g_xh [NX];            // X fp16 (QKV GEMM A)
__device__ __half  g_qh [NX];            // Q fp16
__device__ __half  g_kh [NX];            // K fp16
__device__ __half  g_vh [NX];            // V fp16, row-major [s][hd]
__device__ __half  g_wq [NWQ];           // Wqkv fp16, K-major [K][3E]
__device__ __half  g_wp [NWP];           // Wproj fp16, K-major [K][E]
__device__ __half  g_oh [NX];            // attention output fp16 (proj A)

// ---------------- helpers ----------------
__device__ __forceinline__ void mma16816(float* c, const uint32_t* a, const uint32_t* b)
{
    asm volatile(
        "mma.sync.aligned.m16n8k16.row.col.f32.f16.f16.f32 "
        "{%0,%1,%2,%3}, {%4,%5,%6,%7}, {%8,%9}, {%0,%1,%2,%3};"
        : "+f"(c[0]), "+f"(c[1]), "+f"(c[2]), "+f"(c[3])
        : "r"(a[0]), "r"(a[1]), "r"(a[2]), "r"(a[3]), "r"(b[0]), "r"(b[1]));
}
__device__ __forceinline__ void ldsm4(uint32_t& r0, uint32_t& r1, uint32_t& r2, uint32_t& r3,
                                      uint32_t addr)
{
    asm volatile("ldmatrix.sync.aligned.m8n8.x4.shared.b16 {%0,%1,%2,%3}, [%4];"
                 : "=r"(r0), "=r"(r1), "=r"(r2), "=r"(r3) : "r"(addr));
}
__device__ __forceinline__ void ldsm4t(uint32_t& r0, uint32_t& r1, uint32_t& r2, uint32_t& r3,
                                       uint32_t addr)
{
    asm volatile("ldmatrix.sync.aligned.m8n8.x4.trans.shared.b16 {%0,%1,%2,%3}, [%4];"
                 : "=r"(r0), "=r"(r1), "=r"(r2), "=r"(r3) : "r"(addr));
}
__device__ __forceinline__ void cp16(uint32_t saddr, const void* g)
{
    asm volatile("cp.async.cg.shared.global [%0], [%1], 16;"
                 :: "r"(saddr), "l"(g));
}
__device__ __forceinline__ uint32_t smem_u32(const void* p) {
    uint32_t a;
    asm("{ .reg .u64 t; cvta.to.shared.u64 t, %1; cvt.u32.u64 %0, t; }"
        : "=r"(a) : "l"(p));
    return a;
}
__device__ __forceinline__ uint32_t pack2h(float f0, float f1)
{
    __half2 p = __floats2half2_rn(f0, f1);
    return *(uint32_t*)&p;
}

// ---------------- fused prep: all fp32 -> fp16 converts in one kernel ----------------
__global__ __launch_bounds__(256)
void prep_all(const float* __restrict__ X, const float* __restrict__ Wq,
              const float* __restrict__ Wp,
              __half* __restrict__ xh, __half* __restrict__ wq, __half* __restrict__ wp)
{
    int i4 = (blockIdx.x * 256 + threadIdx.x) * 4;
    const float* src;
    __half* dst;
    int off;
    if (i4 < NX)            { src = X;  dst = xh; off = i4; }
    else if (i4 < NX + NWQ) { src = Wq; dst = wq; off = i4 - NX; }
    else                    { src = Wp; dst = wp; off = i4 - NX - NWQ; }
    float4 v = *(const float4*)(src + off);
    __half hh[4] = {__float2half_rn(v.x), __float2half_rn(v.y),
                    __float2half_rn(v.z), __float2half_rn(v.w)};
    *(uint2*)(dst + off) = *(uint2*)hh;
}

// ---------------- fp16 GEMM: 128x128, 4 warps, 3-stage, K-major B via ldsm.trans ----------------
#define GBK      32
#define GSTRIDE  40
#define ROWB     (GSTRIDE * 2)             // A row: 80 B
#define ARR_A    (128 * ROWB)              // 10240 B
#define BROWB    272                       // B row: 128 fp16 + 8 pad = 272 B
#define ARR_B2   (GBK * BROWB)             // 8704 B
#define STAGE_B  (ARR_A + ARR_B2)          // 18944 B
#define GEMM_SMEM (3 * STAGE_B)            // 56832 B (3-stage, 2 CTAs/SM)

template<bool FUSE>
__global__ __launch_bounds__(128, 2)
void gemm_mma(const __half* __restrict__ A, const __half* __restrict__ B,
              const float* __restrict__ bias, float* __restrict__ C, int N,
              __half* __restrict__ qh, __half* __restrict__ kh, __half* __restrict__ vh)
{
    extern __shared__ char smem[];
    const uint32_t sb = smem_u32(smem);
    const int tid  = threadIdx.x;
    const int wid  = tid >> 5, lane = tid & 31;
    const int wm   = wid >> 1, wn = wid & 1;
    const int g    = lane >> 2, tig = lane & 3;
    const int bm   = blockIdx.y * 128, bn = blockIdx.x * 128;
    const int NC   = Kdim / GBK;

    const int qd = lane >> 3, il = lane & 7;
    const uint32_t offA  = (uint32_t)((wm * 64 + il + (qd & 1) * 8) * ROWB + ((qd >> 1) * 8) * 2);
    const uint32_t offBt = (uint32_t)((il + (qd & 1) * 8) * BROWB + (wn * 64 + (qd >> 1) * 8) * 2);

    float acc[4][8][4];
#pragma unroll
    for (int im = 0; im < 4; im++)
#pragma unroll
        for (int in = 0; in < 8; in++)
#pragma unroll
            for (int q = 0; q < 4; q++) acc[im][in][q] = 0.0f;

    auto prefetch = [&](int c) {
        const int st = c % 3;
#pragma unroll
        for (int i = 0; i < 8; i++) {
            int idx = tid + i * 128;
            const __half* gp;
            uint32_t sa;
            if (idx < 512) {                // A: 128 rows x 64 B
                int row = idx >> 2, seg = idx & 3;
                gp = A + (size_t)(bm + row) * Kdim + (size_t)c * GBK + seg * 8;
                sa = sb + st * STAGE_B + row * ROWB + seg * 16;
            } else {                        // B: 32 k-rows x 256 B (K-major)
                int e = idx - 512;
                int krow = e >> 4, u = e & 15;
                gp = B + (size_t)(c * GBK + krow) * N + bn + u * 8;
                sa = sb + st * STAGE_B + ARR_A + krow * BROWB + u * 16;
            }
            cp16(sa, gp);
        }
        asm volatile("cp.async.commit_group;");
    };

    prefetch(0);

    for (int c = 0; c < NC; c++) {
        const int st = c % 3;
        if (c + 1 < NC) {
            prefetch(c + 1);
            asm volatile("cp.async.wait_group 1;");
        } else {
            asm volatile("cp.async.wait_group 0;");
        }
        __syncthreads();

        const uint32_t stb = sb + st * STAGE_B;

        uint32_t a[2][4][4], bf[2][8][2];
#pragma unroll
        for (int s2 = 0; s2 < 2; s2++) {
            const uint32_t kbA = (uint32_t)(s2 * 32);
            const uint32_t kbB = (uint32_t)(s2 * 16 * BROWB);
#pragma unroll
            for (int p = 0; p < 4; p++)
                ldsm4t(bf[s2][2*p][0], bf[s2][2*p][1], bf[s2][2*p+1][0], bf[s2][2*p+1][1],
                       stb + ARR_A + offBt + kbB + p * 32);
#pragma unroll
            for (int im = 0; im < 4; im++)
                ldsm4(a[s2][im][0], a[s2][im][1], a[s2][im][2], a[s2][im][3],
                      stb + offA + im * (16 * ROWB) + kbA);
        }
#pragma unroll
        for (int s2 = 0; s2 < 2; s2++)
#pragma unroll
            for (int im = 0; im < 4; im++)
#pragma unroll
                for (int in = 0; in < 8; in++)
                    mma16816(acc[im][in], a[s2][im], bf[s2][in]);
    }

    // epilogue
    __half* d = qh;
    if (FUSE) {
        int sec = bn >> 10;
        if (sec == 1) d = kh;
        else if (sec == 2) d = vh;
    }
#pragma unroll
    for (int im = 0; im < 4; im++) {
        int r = bm + wm * 64 + im * 16 + g;
#pragma unroll
        for (int in = 0; in < 8; in++) {
            int ccol = bn + wn * 64 + in * 8 + 2 * tig;
            float2 b01 = *(const float2*)&bias[ccol];
            float2 o0 = make_float2(acc[im][in][0] + b01.x, acc[im][in][1] + b01.y);
            float2 o1 = make_float2(acc[im][in][2] + b01.x, acc[im][in][3] + b01.y);
            if (!FUSE) {
                *(float2*)&C[(size_t)r * N + ccol]       = o0;
                *(float2*)&C[(size_t)(r + 8) * N + ccol] = o1;
            } else {
                int col = ccol & 1023;
                *(uint32_t*)&d[(size_t)r * 1024 + col]       = pack2h(o0.x, o0.y);
                *(uint32_t*)&d[(size_t)(r + 8) * 1024 + col] = pack2h(o1.x, o1.y);
            }
        }
    }
}

// ---------------- fp16 flash attention: 64-row Q tiles, 4 warps, 3 CTAs/SM ----------------
#define AKVROW 144
#define AARR   9216
#define AST    (2 * AARR)                  // 18432
#define ATTN_SMEM (3 * AST)                // 55296 (x3 CTAs = 165.9 KB/SM)

__global__ __launch_bounds__(128, 3)
void attn_mma(const __half* __restrict__ qh,
              const __half* __restrict__ kh, const __half* __restrict__ vh,
              const int* __restrict__ mask, __half* __restrict__ oh)
{
    extern __shared__ char asmem[];
    __shared__ int sMask[3][64];
    const uint32_t sb = smem_u32(asmem);
    const uint32_t mb = smem_u32(&sMask[0][0]);

    const int tid = threadIdx.x, wid = tid >> 5, lane = tid & 31;
    const int g = lane >> 2, tig = lane & 3;
    const int qd = lane >> 3, il = lane & 7;
    const uint32_t offKV  = (uint32_t)((il + (qd >> 1) * 8) * AKVROW + ((qd & 1) * 8) * 2);
    const uint32_t offKVt = (uint32_t)((il + (qd & 1) * 8) * AKVROW + ((qd >> 1) * 8) * 2);

    const int qt = gridDim.x - 1 - blockIdx.x;   // heavy tiles launch first (qt 0..15)
    const int bh = blockIdx.y;
    const int b = bh >> 4, h = bh & 15;
    const int q0 = qt * 64;
    const int wrow = q0 + wid * 16;              // 4 warps x 16 rows = 64
    const float scale = 0.125f;

    // resident Q fragments
    uint32_t aq[4][4];
    {
        const __half* qb = qh + (size_t)(b * Ss + wrow) * Ee + h * 64;
#pragma unroll
        for (int s = 0; s < 4; s++) {
            int k0 = s * 16 + 2 * tig;
            aq[s][0] = *(const uint32_t*)&qb[(size_t)(g    ) * Ee + k0];
            aq[s][1] = *(const uint32_t*)&qb[(size_t)(g + 8) * Ee + k0];
            aq[s][2] = *(const uint32_t*)&qb[(size_t)(g    ) * Ee + k0 + 8];
            aq[s][3] = *(const uint32_t*)&qb[(size_t)(g + 8) * Ee + k0 + 8];
        }
    }

    auto prefetch = [&](int j) {
        const int kv0 = j * 64;
        const int st = j % 3;
        const uint32_t stb = sb + st * AST;
        // 2 arrays x 64 rows x 8 x 16B = 1024 units; 8 per thread (128 threads)
#pragma unroll
        for (int i = 0; i < 8; i++) {
            int idx = tid + i * 128;
            int arr = idx >> 9;             // 0:K 1:V
            int e   = idx & 511;
            int row = e >> 3;
            int segB = (e & 7) * 16;
            const __half* gp = (arr == 0 ? kh : vh)
                             + (size_t)(b * Ss + kv0 + row) * Ee + h * 64 + segB / 2;
            cp16(stb + arr * AARR + row * AKVROW + segB, gp);
        }
        if (tid < 16)
            cp16(mb + st * 256 + tid * 16, &mask[b * Ss + kv0 + tid * 4]);
        asm volatile("cp.async.commit_group;");
    };

    float m0 = -1e30f, m1 = -1e30f, l0 = 0.0f, l1 = 0.0f;
    float o[8][4];
#pragma unroll
    for (int t = 0; t < 8; t++)
#pragma unroll
        for (int e = 0; e < 4; e++) o[t][e] = 0.0f;

    const int row0 = wrow + g, row1 = wrow + 8 + g;
    const int ntiles = qt + 1;

    prefetch(0);

    for (int j = 0; j < ntiles; j++) {
        const int kv0 = j * 64;
        const int st = j % 3;
        if (j + 1 < ntiles) {
            prefetch(j + 1);
            asm volatile("cp.async.wait_group 1;");
        } else {
            asm volatile("cp.async.wait_group 0;");
        }
        __syncthreads();

        const uint32_t stb = sb + st * AST;
        const int* msk = sMask[st];

        // ---- S = Q K^T ----
        float c[8][4];
#pragma unroll
        for (int t = 0; t < 8; t++)
#pragma unroll
            for (int e = 0; e < 4; e++) c[t][e] = 0.0f;

#pragma unroll
        for (int s = 0; s < 4; s++) {
            const uint32_t kb = (uint32_t)(s * 32);
            uint32_t kf[8][2];
#pragma unroll
            for (int p = 0; p < 4; p++)
                ldsm4(kf[2*p][0], kf[2*p][1], kf[2*p+1][0], kf[2*p+1][1],
                      stb + offKV + p * (16 * AKVROW) + kb);
#pragma unroll
            for (int t = 0; t < 8; t++)
                mma16816(c[t], aq[s], kf[t]);
        }

        // ---- scale + causal + key mask ----
#pragma unroll
        for (int t = 0; t < 8; t++) {
            int lc0 = t * 8 + 2 * tig;
            int col0 = kv0 + lc0, col1 = col0 + 1;
            bool v0 = msk[lc0] != 0, v1 = msk[lc0 + 1] != 0;
            c[t][0] = (v0 && col0 <= row0) ? c[t][0] * scale : -1e30f;
            c[t][1] = (v1 && col1 <= row0) ? c[t][1] * scale : -1e30f;
            c[t][2] = (v0 && col0 <= row1) ? c[t][2] * scale : -1e30f;
            c[t][3] = (v1 && col1 <= row1) ? c[t][3] * scale : -1e30f;
        }

        // ---- online softmax ----
        float ml0 = -1e30f, ml1 = -1e30f;
#pragma unroll
        for (int t = 0; t < 8; t++) {
            ml0 = fmaxf(ml0, fmaxf(c[t][0], c[t][1]));
            ml1 = fmaxf(ml1, fmaxf(c[t][2], c[t][3]));
        }
        ml0 = fmaxf(ml0, __shfl_xor_sync(0xffffffffu, ml0, 1));
        ml0 = fmaxf(ml0, __shfl_xor_sync(0xffffffffu, ml0, 2));
        ml1 = fmaxf(ml1, __shfl_xor_sync(0xffffffffu, ml1, 1));
        ml1 = fmaxf(ml1, __shfl_xor_sync(0xffffffffu, ml1, 2));

        float mn0 = fmaxf(m0, ml0), mn1 = fmaxf(m1, ml1);
        float alpha0 = __expf(m0 - mn0), alpha1 = __expf(m1 - mn1);
        m0 = mn0; m1 = mn1;

        float rs0 = 0.0f, rs1 = 0.0f;
#pragma unroll
        for (int t = 0; t < 8; t++) {
            c[t][0] = __expf(c[t][0] - m0); rs0 += c[t][0];
            c[t][1] = __expf(c[t][1] - m0); rs0 += c[t][1];
            c[t][2] = __expf(c[t][2] - m1); rs1 += c[t][2];
            c[t][3] = __expf(c[t][3] - m1); rs1 += c[t][3];
        }
        rs0 += __shfl_xor_sync(0xffffffffu, rs0, 1);
        rs0 += __shfl_xor_sync(0xffffffffu, rs0, 2);
        rs1 += __shfl_xor_sync(0xffffffffu, rs1, 1);
        rs1 += __shfl_xor_sync(0xffffffffu, rs1, 2);

        l0 = l0 * alpha0 + rs0;
        l1 = l1 * alpha1 + rs1;
#pragma unroll
        for (int t = 0; t < 8; t++) {
            o[t][0] *= alpha0; o[t][1] *= alpha0;
            o[t][2] *= alpha1; o[t][3] *= alpha1;
        }

        // ---- O += P V (V via ldmatrix.trans) ----
#pragma unroll
        for (int s = 0; s < 4; s++) {
            uint32_t ap[4];
            ap[0] = pack2h(c[2 * s][0],     c[2 * s][1]);
            ap[1] = pack2h(c[2 * s][2],     c[2 * s][3]);
            ap[2] = pack2h(c[2 * s + 1][0], c[2 * s + 1][1]);
            ap[3] = pack2h(c[2 * s + 1][2], c[2 * s + 1][3]);
            const uint32_t krow = (uint32_t)(s * 16 * AKVROW);
            uint32_t vf[8][2];
#pragma unroll
            for (int p = 0; p < 4; p++)
                ldsm4t(vf[2*p][0], vf[2*p][1], vf[2*p+1][0], vf[2*p+1][1],
                       stb + AARR + offKVt + krow + p * 32);
#pragma unroll
            for (int t = 0; t < 8; t++)
                mma16816(o[t], ap, vf[t]);
        }
    }

    // epilogue: write fp16 output
    float inv0 = 1.0f / l0, inv1 = 1.0f / l1;
    size_t base0 = (size_t)(b * Ss + row0) * Ee + h * 64;
    size_t base1 = (size_t)(b * Ss + row1) * Ee + h * 64;
#pragma unroll
    for (int t = 0; t < 8; t++) {
        int cc = t * 8 + 2 * tig;
        *(uint32_t*)&oh[base0 + cc] = pack2h(o[t][0] * inv0, o[t][1] * inv0);
        *(uint32_t*)&oh[base1 + cc] = pack2h(o[t][2] * inv1, o[t][3] * inv1);
    }
}

// ---------------- launch ----------------
extern "C" void kernel_launch(void* const* d_in, const int* in_sizes, int n_in,
                              void* d_out, int out_size)
{
    const float* X     = (const float*)d_in[0];
    const int*   mask  = (const int*)  d_in[1];
    const float* Wqkv  = (const float*)d_in[2];
    const float* bqkv  = (const float*)d_in[3];
    const float* Wproj = (const float*)d_in[4];
    const float* bproj = (const float*)d_in[5];
    float* out = (float*)d_out;

    __half *xh, *qh, *kh, *vh, *wq, *wp, *oh;
    cudaGetSymbolAddress((void**)&xh, g_xh);
    cudaGetSymbolAddress((void**)&qh, g_qh);
    cudaGetSymbolAddress((void**)&kh, g_kh);
    cudaGetSymbolAddress((void**)&vh, g_vh);
    cudaGetSymbolAddress((void**)&wq, g_wq);
    cudaGetSymbolAddress((void**)&wp, g_wp);
    cudaGetSymbolAddress((void**)&oh, g_oh);

    cudaFuncSetAttribute(gemm_mma<true>,  cudaFuncAttributeMaxDynamicSharedMemorySize, GEMM_SMEM);
    cudaFuncSetAttribute(gemm_mma<false>, cudaFuncAttributeMaxDynamicSharedMemorySize, GEMM_SMEM);
    cudaFuncSetAttribute(attn_mma, cudaFuncAttributeMaxDynamicSharedMemorySize, ATTN_SMEM);

    // prep: all converts in ONE kernel
    prep_all<<<(NX + NWQ + NWP) / 4 / 256, 256>>>(X, Wqkv, Wproj, xh, wq, wp);

    // 1) QKV = X @ Wqkv + b (fp16), fused epilogue -> q/k/v fp16
    gemm_mma<true><<<dim3(E3 / 128, MTOT / 128), 128, GEMM_SMEM>>>(
        xh, wq, bqkv, nullptr, E3, qh, kh, vh);

    // 2) flash attention (64-row Q tiles, 3 CTAs/SM)
    attn_mma<<<dim3(Ss / 64, Bb * Hh), 128, ATTN_SMEM>>>(qh, kh, vh, mask, oh);

    // 3) out = attn @ Wproj + b (fp16, fp32 out)
    gemm_mma<false><<<dim3(Ee / 128, MTOT / 128), 128, GEMM_SMEM>>>(
        oh, wp, bproj, out, Ee, qh, kh, vh);
}